// round 10
// baseline (speedup 1.0000x reference)
#include <cuda_runtime.h>
#include <cuda_fp16.h>
#include <math.h>
#include <stdint.h>

// VanillaVQ: z_e (8,64,64,64) fp32, embedding (8192,64) fp32.
// Outputs (concat fp32): z_q | indices | commit_loss | perplexity | usage.

#define K_CODES 8192
#define D_DIM   64
#define N_ROWS  32768
#define HW      4096
#define BETA    0.25f
#define NZ (N_ROWS * D_DIM)
#define NI N_ROWS
#define EPS_GAP 5e-4f

// GEMM config: S = fp16(z).fp16(e) (KD=64, certified by gap test)
#define M_CTA  128
#define CTAS   256
#define NTH    512          // 16 warps: 4(M) x 4(N); warp tile 32x32
#define NT     128          // codes per chunk
#define NCH    64
#define ARS    144          // row strides (16 mod 128 -> conflict-free ldmatrix)
#define BRS    144
#define SM_A   0            // 128*144 = 18432
#define SM_B(i) (18432u + (uint32_t)(i) * 18432u)   // 3 bufs
#define SM_TOT 73728

// ---------------- device scratch ----------------
__device__ float g_b2[K_CODES];
__device__ int   g_counts[K_CODES];
__device__ float g_loss;
__device__ int   g_nflag;
__device__ int   g_idx[N_ROWS];
__device__ int   g_flagrows[N_ROWS];
__device__ float g_pval[N_ROWS * 64];
__device__ int   g_pidx[N_ROWS * 64];
__device__ __align__(128) uint32_t g_E[K_CODES * 32];   // 1MB fp16 image of emb

// ---------------- helpers ----------------
__device__ __forceinline__ uint32_t smem_u32(const void* p) {
    uint32_t a;
    asm("{ .reg .u64 t; cvta.to.shared.u64 t, %1; cvt.u32.u64 %0, t; }" : "=r"(a) : "l"(p));
    return a;
}
__device__ __forceinline__ uint32_t packh(float a, float b) {
    __half2 h = __floats2half2_rn(a, b);
    return *reinterpret_cast<uint32_t*>(&h);
}
__device__ __forceinline__ void ldm_x4(uint32_t* r, uint32_t addr) {
    asm volatile("ldmatrix.sync.aligned.m8n8.x4.shared.b16 {%0,%1,%2,%3}, [%4];"
                 : "=r"(r[0]), "=r"(r[1]), "=r"(r[2]), "=r"(r[3]) : "r"(addr));
}
__device__ __forceinline__ void ldm_x2(uint32_t* r, uint32_t addr) {
    asm volatile("ldmatrix.sync.aligned.m8n8.x2.shared.b16 {%0,%1}, [%2];"
                 : "=r"(r[0]), "=r"(r[1]) : "r"(addr));
}
__device__ __forceinline__ void mma16816(float* c, const uint32_t* a, const uint32_t* b) {
    asm volatile(
        "mma.sync.aligned.m16n8k16.row.col.f32.f16.f16.f32 "
        "{%0,%1,%2,%3}, {%4,%5,%6,%7}, {%8,%9}, {%0,%1,%2,%3};"
        : "+f"(c[0]), "+f"(c[1]), "+f"(c[2]), "+f"(c[3])
        : "r"(a[0]), "r"(a[1]), "r"(a[2]), "r"(a[3]), "r"(b[0]), "r"(b[1]));
}
__device__ __forceinline__ void cp16(uint32_t dst, const void* src) {
    uint64_t gs; asm("cvta.to.global.u64 %0, %1;" : "=l"(gs) : "l"(src));
    asm volatile("cp.async.cg.shared.global [%0], [%1], 16;" :: "r"(dst), "l"(gs));
}

// ---------------------------------------------------------------------------
// Kernel 1: b2 in XLA warp-tree order (warp per code) + zero accumulators
// ---------------------------------------------------------------------------
__global__ void vq_prep_b2(const float* __restrict__ emb) {
    int gtid = blockIdx.x * blockDim.x + threadIdx.x;
    int k = gtid >> 5, lane = gtid & 31;
    if (k < K_CODES) {
        const float* e = emb + (size_t)k * D_DIM;
        float t = __fadd_rn(__fmul_rn(e[lane], e[lane]),
                            __fmul_rn(e[lane + 32], e[lane + 32]));
#pragma unroll
        for (int off = 16; off >= 1; off >>= 1)
            t = __fadd_rn(t, __shfl_down_sync(0xFFFFFFFFu, t, off));
        if (lane == 0) { g_b2[k] = t; g_counts[k] = 0; }
    }
    if (gtid == 0) { g_loss = 0.0f; g_nflag = 0; }
}

// ---------------------------------------------------------------------------
// Kernel 2: fp16 image of emb (64 fp16 per code, 128B row)
// ---------------------------------------------------------------------------
__global__ void vq_prep_e(const float* __restrict__ emb) {
    int k = blockIdx.x * blockDim.x + threadIdx.x;
    if (k >= K_CODES) return;
    uint32_t* base = g_E + (size_t)k * 32;
    const float* e = emb + (size_t)k * D_DIM;
#pragma unroll 8
    for (int j = 0; j < 32; j++)
        base[j] = packh(e[2 * j], e[2 * j + 1]);
}

// ---------------------------------------------------------------------------
// Kernel 3: fp16 HMMA GEMM  S = z.e - 0.5*b2  + running top-2 + gap flag
// 256 CTAs x 512 threads (4M x 4N warps), warp tile 32x32, A in regs.
// ---------------------------------------------------------------------------
__device__ __forceinline__ void copy_chunk(int c, uint32_t dstbase, int tid) {
    const char* src = (const char*)g_E + (size_t)c * (NT * 128);
#pragma unroll
    for (int t = 0; t < 2; t++) {
        int idx = tid + t * NTH;                 // 0..1023
        int row = idx >> 3, seg = idx & 7;
        cp16(dstbase + (uint32_t)row * BRS + (uint32_t)seg * 16,
             src + (size_t)row * 128 + (size_t)seg * 16);
    }
}

__global__ __launch_bounds__(NTH, 1)
void vq_gemm(const float* __restrict__ z) {
    extern __shared__ __align__(128) char smem[];
    const uint32_t sb = smem_u32(smem);
    const int tid = threadIdx.x, cta = blockIdx.x;
    const int lane = tid & 31, warp = tid >> 5;
    const int wm = warp >> 2, wn = warp & 3;      // 4(M) x 4(N)

    // ---- build A tile: row r (<128): 64 fp16 of z ----
    if (tid < M_CTA) {
        int grow = cta * M_CTA + tid;
        const float* zp = z + (size_t)(grow >> 12) * (D_DIM * HW) + (grow & 4095);
        char* ar = smem + SM_A + (size_t)tid * ARS;
#pragma unroll 8
        for (int d = 0; d < 64; d += 2)
            *(uint32_t*)(ar + 2 * d) = packh(zp[(size_t)d * HW], zp[(size_t)(d + 1) * HW]);
    }
    __syncthreads();

    // ---- hoist A fragments to registers (chunk-invariant) ----
    const uint32_t Abase = sb + SM_A
        + (uint32_t)(wm * 32 + (lane & 7) + ((lane >> 3) & 1) * 8) * ARS
        + ((lane >> 4) & 1) * 16;
    uint32_t afr[4][2][4];
#pragma unroll
    for (int kk = 0; kk < 4; kk++)
#pragma unroll
        for (int mf = 0; mf < 2; mf++)
            ldm_x4(afr[kk][mf], Abase + (uint32_t)mf * (16 * ARS) + (uint32_t)kk * 32);

    copy_chunk(0, sb + SM_B(0), tid);
    asm volatile("cp.async.commit_group;");
    copy_chunk(1, sb + SM_B(1), tid);
    asm volatile("cp.async.commit_group;");

    const int bl = lane & 15;
    const uint32_t Bofs = (uint32_t)(wn * 32 + (bl & 7)) * BRS + ((bl >> 3) & 1) * 16;

    float m1[4], m2[4]; int k1[4];
#pragma unroll
    for (int i = 0; i < 4; i++) { m1[i] = -3.4e38f; m2[i] = -3.4e38f; k1[i] = 0; }

    for (int c = 0; c < NCH; c++) {
        const uint32_t bbase = sb + SM_B(c % 3);
        if (c == NCH - 1) asm volatile("cp.async.wait_group 0;");
        else              asm volatile("cp.async.wait_group 1;");
        __syncthreads();     // chunk c visible; buf (c+2)%3 free
        if (c + 2 < NCH) {
            copy_chunk(c + 2, sb + SM_B((c + 2) % 3), tid);
            asm volatile("cp.async.commit_group;");
        }

        float acc[2][4][4];
#pragma unroll
        for (int mf = 0; mf < 2; mf++)
#pragma unroll
            for (int nf = 0; nf < 4; nf++)
#pragma unroll
                for (int v = 0; v < 4; v++) acc[mf][nf][v] = 0.0f;

#pragma unroll
        for (int kk = 0; kk < 4; kk++) {
            uint32_t b[4][2];
#pragma unroll
            for (int nf = 0; nf < 4; nf++)
                ldm_x2(b[nf], bbase + Bofs + (uint32_t)nf * (8 * BRS) + (uint32_t)kk * 32);
#pragma unroll
            for (int mf = 0; mf < 2; mf++)
#pragma unroll
                for (int nf = 0; nf < 4; nf++)
                    mma16816(acc[mf][nf], afr[kk][mf], b[nf]);
        }

        // epilogue: s = acc - 0.5*b2, per-row top-2 (min/max form)
#pragma unroll
        for (int nf = 0; nf < 4; nf++) {
            const int ng = c * NT + wn * 32 + nf * 8 + (lane & 3) * 2;
            const float2 bv = *(const float2*)&g_b2[ng];
#pragma unroll
            for (int mf = 0; mf < 2; mf++) {
                const int r0 = mf * 2, r1 = mf * 2 + 1;
                float s, o;
                s = fmaf(-0.5f, bv.x, acc[mf][nf][0]);
                o = m1[r0]; m2[r0] = fmaxf(m2[r0], fminf(s, o));
                if (s > o) { m1[r0] = s; k1[r0] = ng; }
                s = fmaf(-0.5f, bv.y, acc[mf][nf][1]);
                o = m1[r0]; m2[r0] = fmaxf(m2[r0], fminf(s, o));
                if (s > o) { m1[r0] = s; k1[r0] = ng + 1; }
                s = fmaf(-0.5f, bv.x, acc[mf][nf][2]);
                o = m1[r1]; m2[r1] = fmaxf(m2[r1], fminf(s, o));
                if (s > o) { m1[r1] = s; k1[r1] = ng; }
                s = fmaf(-0.5f, bv.y, acc[mf][nf][3]);
                o = m1[r1]; m2[r1] = fmaxf(m2[r1], fminf(s, o));
                if (s > o) { m1[r1] = s; k1[r1] = ng + 1; }
            }
        }
    }

    // merge across the 4 quad lanes (same rows, different cols)
#pragma unroll
    for (int off = 1; off <= 2; off <<= 1) {
#pragma unroll
        for (int i = 0; i < 4; i++) {
            float om1 = __shfl_xor_sync(0xFFFFFFFFu, m1[i], off);
            float om2 = __shfl_xor_sync(0xFFFFFFFFu, m2[i], off);
            int   ok  = __shfl_xor_sync(0xFFFFFFFFu, k1[i], off);
            if (om1 > m1[i]) { m2[i] = fmaxf(m1[i], om2); m1[i] = om1; k1[i] = ok; }
            else             { m2[i] = fmaxf(m2[i], om1); }
        }
    }

    __syncthreads();   // smem reuse for cross-warp reduction
    float* RM1 = (float*)smem;                 // [128][4]
    float* RM2 = (float*)(smem + 2048);
    int*   RK  = (int*)(smem + 4096);
    if ((lane & 3) == 0) {
#pragma unroll
        for (int mf = 0; mf < 2; mf++)
#pragma unroll
            for (int h = 0; h < 2; h++) {
                int ri = mf * 2 + h;
                int rl = wm * 32 + mf * 16 + h * 8 + (lane >> 2);
                RM1[rl * 4 + wn] = m1[ri];
                RM2[rl * 4 + wn] = m2[ri];
                RK [rl * 4 + wn] = k1[ri];
            }
    }
    __syncthreads();
    if (tid < M_CTA) {
        float f1 = RM1[tid * 4], f2 = RM2[tid * 4]; int fk = RK[tid * 4];
#pragma unroll
        for (int w = 1; w < 4; w++) {
            float o1 = RM1[tid * 4 + w], o2 = RM2[tid * 4 + w]; int ok = RK[tid * 4 + w];
            if (o1 > f1) { f2 = fmaxf(f1, o2); f1 = o1; fk = ok; }
            else         { f2 = fmaxf(f2, o1); }
        }
        int grow = cta * M_CTA + tid;
        g_idx[grow] = fk;
        if (f1 - f2 < EPS_GAP) { int p = atomicAdd(&g_nflag, 1); g_flagrows[p] = grow; }
    }
}

// ---------------------------------------------------------------------------
// Kernel 4: parallel fallback — grid (64 tiles, 16 row-groups), bit-exact dist
// (a2 recomputed in-block via the exact XLA shfl tree — bitwise identical)
// ---------------------------------------------------------------------------
__global__ __launch_bounds__(128)
void vq_fb_part(const float* __restrict__ z, const float* __restrict__ emb) {
    __shared__ float ec[128][68];
    __shared__ float zrow[64];
    __shared__ float b2c[128];
    __shared__ float wv[4];
    __shared__ int   wk[4];
    __shared__ float sa2;
    const int tid = threadIdx.x, t = blockIdx.x, grp = blockIdx.y;
    const int nf = g_nflag;
    if (grp >= nf) return;

    {
        const float4* g = (const float4*)(emb + (size_t)(t * 128 + tid) * D_DIM);
        float4* d = (float4*)&ec[tid][0];
#pragma unroll
        for (int i = 0; i < 16; i++) d[i] = g[i];
        b2c[tid] = g_b2[t * 128 + tid];
    }
    __syncthreads();

    for (int fi = grp; fi < nf; fi += 16) {
        if (tid < 64) {
            int row = g_flagrows[fi];
            zrow[tid] = z[(size_t)(row >> 12) * (D_DIM * HW) + (size_t)tid * HW + (row & 4095)];
        }
        __syncthreads();
        if (tid < 32) {   // exact a2: XLA warp-tree order
            float tt = __fadd_rn(__fmul_rn(zrow[tid], zrow[tid]),
                                 __fmul_rn(zrow[tid + 32], zrow[tid + 32]));
#pragma unroll
            for (int off = 16; off >= 1; off >>= 1)
                tt = __fadd_rn(tt, __shfl_down_sync(0xFFFFFFFFu, tt, off));
            if (tid == 0) sa2 = tt;
        }
        __syncthreads();
        float acc = 0.0f;
        const float4* zb = (const float4*)&zrow[0];
        const float4* eb = (const float4*)&ec[tid][0];
#pragma unroll
        for (int i = 0; i < 16; i++) {
            float4 zv = zb[i], ev = eb[i];
            acc = fmaf(zv.x, ev.x, acc); acc = fmaf(zv.y, ev.y, acc);
            acc = fmaf(zv.z, ev.z, acc); acc = fmaf(zv.w, ev.w, acc);
        }
        float dist = __fadd_rn(__fsub_rn(sa2, __fmul_rn(2.0f, acc)), b2c[tid]);
        int   kidx = t * 128 + tid;
#pragma unroll
        for (int off = 16; off >= 1; off >>= 1) {
            float ov = __shfl_down_sync(0xFFFFFFFFu, dist, off);
            int   ok = __shfl_down_sync(0xFFFFFFFFu, kidx, off);
            if (ov < dist || (ov == dist && ok < kidx)) { dist = ov; kidx = ok; }
        }
        if ((tid & 31) == 0) { wv[tid >> 5] = dist; wk[tid >> 5] = kidx; }
        __syncthreads();
        if (tid == 0) {
            float bv = wv[0]; int bk = wk[0];
#pragma unroll
            for (int w = 1; w < 4; w++)
                if (wv[w] < bv || (wv[w] == bv && wk[w] < bk)) { bv = wv[w]; bk = wk[w]; }
            g_pval[(size_t)fi * 64 + t] = bv;
            g_pidx[(size_t)fi * 64 + t] = bk;
        }
        __syncthreads();
    }
}

// ---------------------------------------------------------------------------
// Kernel 5: fallback reduce — warp per flagged row over 64 tile results
// ---------------------------------------------------------------------------
__global__ void vq_fb_red() {
    int nf = g_nflag;
    int gw = (blockIdx.x * blockDim.x + threadIdx.x) >> 5;
    int lane = threadIdx.x & 31;
    int nwarps = (gridDim.x * blockDim.x) >> 5;
    for (int fi = gw; fi < nf; fi += nwarps) {
        float v1 = g_pval[(size_t)fi * 64 + lane];
        int   k1 = g_pidx[(size_t)fi * 64 + lane];
        float v2 = g_pval[(size_t)fi * 64 + lane + 32];
        int   k2 = g_pidx[(size_t)fi * 64 + lane + 32];
        if (v2 < v1 || (v2 == v1 && k2 < k1)) { v1 = v2; k1 = k2; }
#pragma unroll
        for (int off = 16; off >= 1; off >>= 1) {
            float ov = __shfl_down_sync(0xFFFFFFFFu, v1, off);
            int   ok = __shfl_down_sync(0xFFFFFFFFu, k1, off);
            if (ov < v1 || (ov == v1 && ok < k1)) { v1 = ov; k1 = ok; }
        }
        if (lane == 0) g_idx[g_flagrows[fi]] = k1;
    }
}

// ---------------------------------------------------------------------------
// Kernel 6: gather + STE z_q + indices + counts + loss
// ---------------------------------------------------------------------------
__global__ __launch_bounds__(256)
void vq_final(const float* __restrict__ z, const float* __restrict__ emb,
              float* __restrict__ out, int out_size) {
    const int row = blockIdx.x * 256 + threadIdx.x;
    const int b = row >> 12, hw = row & 4095;
    const int bidx = g_idx[row];
    const float* zp = z + (size_t)b * (D_DIM * HW) + hw;
    const float* eb = emb + (size_t)bidx * D_DIM;
    float* zq = out + (size_t)b * (D_DIM * HW) + hw;
    const bool wz = (out_size >= NZ);
    float ssq = 0.0f;
#pragma unroll
    for (int d = 0; d < D_DIM; d++) {
        float zv = zp[(size_t)d * HW], ev = eb[d];
        float df = __fsub_rn(zv, ev);
        ssq = fmaf(df, df, ssq);
        if (wz) zq[(size_t)d * HW] = __fadd_rn(zv, __fsub_rn(ev, zv));
    }
    if (out_size >= NZ + NI) out[NZ + row] = (float)bidx;
    atomicAdd(&g_counts[bidx], 1);
#pragma unroll
    for (int o = 16; o > 0; o >>= 1) ssq += __shfl_down_sync(0xFFFFFFFFu, ssq, o);
    if ((threadIdx.x & 31) == 0) atomicAdd(&g_loss, ssq);
}

// ---------------------------------------------------------------------------
// Kernel 7: scalars
// ---------------------------------------------------------------------------
__global__ void vq_finalize(float* __restrict__ out, int out_size) {
    __shared__ float sH[256];
    __shared__ int   sU[256];
    const int tid = threadIdx.x;
    float H = 0.0f; int used = 0;
    for (int k = tid; k < K_CODES; k += 256) {
        float c = (float)g_counts[k];
        if (c > 0.0f) used++;
        float avg = c * (1.0f / (float)N_ROWS);
        H = fmaf(avg, logf(avg + 1e-10f), H);
    }
    sH[tid] = H; sU[tid] = used;
    __syncthreads();
    for (int s = 128; s > 0; s >>= 1) {
        if (tid < s) { sH[tid] += sH[tid + s]; sU[tid] += sU[tid + s]; }
        __syncthreads();
    }
    if (tid == 0 && out_size >= NZ + NI + 3) {
        out[NZ + NI + 0] = BETA * g_loss / (float)(N_ROWS * D_DIM);
        out[NZ + NI + 1] = expf(-sH[0]);
        out[NZ + NI + 2] = (float)sU[0] / (float)K_CODES;
    }
}

// ---------------------------------------------------------------------------
extern "C" void kernel_launch(void* const* d_in, const int* in_sizes, int n_in,
                              void* d_out, int out_size) {
    const float* z   = (const float*)d_in[0];
    const float* emb = (const float*)d_in[1];
    float* out = (float*)d_out;

    cudaFuncSetAttribute(vq_gemm, cudaFuncAttributeMaxDynamicSharedMemorySize, SM_TOT);

    vq_prep_b2<<<(K_CODES * 32) / 256, 256>>>(emb);
    vq_prep_e<<<K_CODES / 256, 256>>>(emb);
    vq_gemm<<<CTAS, NTH, SM_TOT>>>(z);
    vq_fb_part<<<dim3(64, 16), 128>>>(z, emb);
    vq_fb_red<<<64, 256>>>();
    vq_final<<<N_ROWS / 256, 256>>>(z, emb, out, out_size);
    vq_finalize<<<1, 256>>>(out, out_size);
}

// round 11
// speedup vs baseline: 1.1165x; 1.1165x over previous
#include <cuda_runtime.h>
#include <cuda_fp16.h>
#include <math.h>
#include <stdint.h>

// VanillaVQ: z_e (8,64,64,64) fp32, embedding (8192,64) fp32.
// Outputs (concat fp32): z_q | indices | commit_loss | perplexity | usage.

#define K_CODES 8192
#define D_DIM   64
#define N_ROWS  32768
#define HW      4096
#define BETA    0.25f
#define NZ (N_ROWS * D_DIM)
#define NI N_ROWS
#define EPS_GAP 3.5e-4f

// GEMM config: S = fp16(z).fp16(e) (KD=64, certified by gap test)
#define M_CTA  128
#define CTAS   256
#define NTH    512          // 16 warps: 4(M) x 4(N); warp tile 32x32
#define NT     128          // codes per chunk
#define NCH    64
#define ARS    144          // row strides (16 mod 128 -> conflict-free ldmatrix)
#define BRS    144
#define SM_A   0            // 128*144 = 18432
#define SM_B(i) (18432u + (uint32_t)(i) * 18432u)   // 3 bufs
#define SM_TOT 73728

#define FB_GRPS 64          // fallback row-groups (parallelism)

// ---------------- device scratch ----------------
__device__ float g_b2[K_CODES];
__device__ int   g_counts[K_CODES];
__device__ float g_loss;
__device__ int   g_nflag;
__device__ int   g_idx[N_ROWS];
__device__ int   g_flagrows[N_ROWS];
__device__ float g_pval[N_ROWS * 64];
__device__ int   g_pidx[N_ROWS * 64];
__device__ __align__(128) uint32_t g_E[K_CODES * 32];   // 1MB fp16 image of emb

// ---------------- helpers ----------------
__device__ __forceinline__ uint32_t smem_u32(const void* p) {
    uint32_t a;
    asm("{ .reg .u64 t; cvta.to.shared.u64 t, %1; cvt.u32.u64 %0, t; }" : "=r"(a) : "l"(p));
    return a;
}
__device__ __forceinline__ uint32_t packh(float a, float b) {
    __half2 h = __floats2half2_rn(a, b);
    return *reinterpret_cast<uint32_t*>(&h);
}
__device__ __forceinline__ void ldm_x4(uint32_t* r, uint32_t addr) {
    asm volatile("ldmatrix.sync.aligned.m8n8.x4.shared.b16 {%0,%1,%2,%3}, [%4];"
                 : "=r"(r[0]), "=r"(r[1]), "=r"(r[2]), "=r"(r[3]) : "r"(addr));
}
__device__ __forceinline__ void ldm_x2(uint32_t* r, uint32_t addr) {
    asm volatile("ldmatrix.sync.aligned.m8n8.x2.shared.b16 {%0,%1}, [%2];"
                 : "=r"(r[0]), "=r"(r[1]) : "r"(addr));
}
__device__ __forceinline__ void mma16816(float* c, const uint32_t* a, const uint32_t* b) {
    asm volatile(
        "mma.sync.aligned.m16n8k16.row.col.f32.f16.f16.f32 "
        "{%0,%1,%2,%3}, {%4,%5,%6,%7}, {%8,%9}, {%0,%1,%2,%3};"
        : "+f"(c[0]), "+f"(c[1]), "+f"(c[2]), "+f"(c[3])
        : "r"(a[0]), "r"(a[1]), "r"(a[2]), "r"(a[3]), "r"(b[0]), "r"(b[1]));
}
__device__ __forceinline__ void cp16(uint32_t dst, const void* src) {
    uint64_t gs; asm("cvta.to.global.u64 %0, %1;" : "=l"(gs) : "l"(src));
    asm volatile("cp.async.cg.shared.global [%0], [%1], 16;" :: "r"(dst), "l"(gs));
}

// ---------------------------------------------------------------------------
// Kernel 1: b2 in XLA warp-tree order (warp per code)
// ---------------------------------------------------------------------------
__global__ void vq_prep_b2(const float* __restrict__ emb) {
    int gtid = blockIdx.x * blockDim.x + threadIdx.x;
    int k = gtid >> 5, lane = gtid & 31;
    if (k < K_CODES) {
        const float* e = emb + (size_t)k * D_DIM;
        float t = __fadd_rn(__fmul_rn(e[lane], e[lane]),
                            __fmul_rn(e[lane + 32], e[lane + 32]));
#pragma unroll
        for (int off = 16; off >= 1; off >>= 1)
            t = __fadd_rn(t, __shfl_down_sync(0xFFFFFFFFu, t, off));
        if (lane == 0) g_b2[k] = t;
    }
}

// ---------------------------------------------------------------------------
// Kernel 2: zero accumulators
// ---------------------------------------------------------------------------
__global__ void vq_prep_zero() {
    int k = blockIdx.x * blockDim.x + threadIdx.x;
    if (k < K_CODES) g_counts[k] = 0;
    if (k == 0) { g_loss = 0.0f; g_nflag = 0; }
}

// ---------------------------------------------------------------------------
// Kernel 3: fp16 image of emb (64 fp16 per code, 128B row)
// ---------------------------------------------------------------------------
__global__ void vq_prep_e(const float* __restrict__ emb) {
    int k = blockIdx.x * blockDim.x + threadIdx.x;
    if (k >= K_CODES) return;
    uint32_t* base = g_E + (size_t)k * 32;
    const float* e = emb + (size_t)k * D_DIM;
#pragma unroll 8
    for (int j = 0; j < 32; j++)
        base[j] = packh(e[2 * j], e[2 * j + 1]);
}

// ---------------------------------------------------------------------------
// Kernel 4: fp16 HMMA GEMM  S = z.e - 0.5*b2  + running top-2 + gap flag
// 256 CTAs x 512 threads (4M x 4N warps), warp tile 32x32, A re-read per chunk
// (no reg hoist -> no spills at 512 threads).
// ---------------------------------------------------------------------------
__device__ __forceinline__ void copy_chunk(int c, uint32_t dstbase, int tid) {
    const char* src = (const char*)g_E + (size_t)c * (NT * 128);
#pragma unroll
    for (int t = 0; t < 2; t++) {
        int idx = tid + t * NTH;                 // 0..1023
        int row = idx >> 3, seg = idx & 7;
        cp16(dstbase + (uint32_t)row * BRS + (uint32_t)seg * 16,
             src + (size_t)row * 128 + (size_t)seg * 16);
    }
}

__global__ __launch_bounds__(NTH, 1)
void vq_gemm(const float* __restrict__ z) {
    extern __shared__ __align__(128) char smem[];
    const uint32_t sb = smem_u32(smem);
    const int tid = threadIdx.x, cta = blockIdx.x;
    const int lane = tid & 31, warp = tid >> 5;
    const int wm = warp >> 2, wn = warp & 3;      // 4(M) x 4(N)

    // ---- build A tile: row r (<128): 64 fp16 of z ----
    if (tid < M_CTA) {
        int grow = cta * M_CTA + tid;
        const float* zp = z + (size_t)(grow >> 12) * (D_DIM * HW) + (grow & 4095);
        char* ar = smem + SM_A + (size_t)tid * ARS;
#pragma unroll 8
        for (int d = 0; d < 64; d += 2)
            *(uint32_t*)(ar + 2 * d) = packh(zp[(size_t)d * HW], zp[(size_t)(d + 1) * HW]);
    }
    __syncthreads();

    const uint32_t Abase = sb + SM_A
        + (uint32_t)(wm * 32 + (lane & 7) + ((lane >> 3) & 1) * 8) * ARS
        + ((lane >> 4) & 1) * 16;

    copy_chunk(0, sb + SM_B(0), tid);
    asm volatile("cp.async.commit_group;");
    copy_chunk(1, sb + SM_B(1), tid);
    asm volatile("cp.async.commit_group;");

    const int bl = lane & 15;
    const uint32_t Bofs = (uint32_t)(wn * 32 + (bl & 7)) * BRS + ((bl >> 3) & 1) * 16;

    float m1[4], m2[4]; int k1[4];
#pragma unroll
    for (int i = 0; i < 4; i++) { m1[i] = -3.4e38f; m2[i] = -3.4e38f; k1[i] = 0; }

    for (int c = 0; c < NCH; c++) {
        const uint32_t bbase = sb + SM_B(c % 3);
        if (c == NCH - 1) asm volatile("cp.async.wait_group 0;");
        else              asm volatile("cp.async.wait_group 1;");
        __syncthreads();     // chunk c visible; buf (c+2)%3 free
        if (c + 2 < NCH) {
            copy_chunk(c + 2, sb + SM_B((c + 2) % 3), tid);
            asm volatile("cp.async.commit_group;");
        }

        float acc[2][4][4];
#pragma unroll
        for (int mf = 0; mf < 2; mf++)
#pragma unroll
            for (int nf = 0; nf < 4; nf++)
#pragma unroll
                for (int v = 0; v < 4; v++) acc[mf][nf][v] = 0.0f;

#pragma unroll
        for (int kk = 0; kk < 4; kk++) {
            uint32_t b[4][2], a[2][4];
#pragma unroll
            for (int nf = 0; nf < 4; nf++)
                ldm_x2(b[nf], bbase + Bofs + (uint32_t)nf * (8 * BRS) + (uint32_t)kk * 32);
#pragma unroll
            for (int mf = 0; mf < 2; mf++)
                ldm_x4(a[mf], Abase + (uint32_t)mf * (16 * ARS) + (uint32_t)kk * 32);
#pragma unroll
            for (int mf = 0; mf < 2; mf++)
#pragma unroll
                for (int nf = 0; nf < 4; nf++)
                    mma16816(acc[mf][nf], a[mf], b[nf]);
        }

        // epilogue: s = acc - 0.5*b2, per-row top-2 (min/max form)
#pragma unroll
        for (int nf = 0; nf < 4; nf++) {
            const int ng = c * NT + wn * 32 + nf * 8 + (lane & 3) * 2;
            const float2 bv = *(const float2*)&g_b2[ng];
#pragma unroll
            for (int mf = 0; mf < 2; mf++) {
                const int r0 = mf * 2, r1 = mf * 2 + 1;
                float s, o;
                s = fmaf(-0.5f, bv.x, acc[mf][nf][0]);
                o = m1[r0]; m2[r0] = fmaxf(m2[r0], fminf(s, o));
                if (s > o) { m1[r0] = s; k1[r0] = ng; }
                s = fmaf(-0.5f, bv.y, acc[mf][nf][1]);
                o = m1[r0]; m2[r0] = fmaxf(m2[r0], fminf(s, o));
                if (s > o) { m1[r0] = s; k1[r0] = ng + 1; }
                s = fmaf(-0.5f, bv.x, acc[mf][nf][2]);
                o = m1[r1]; m2[r1] = fmaxf(m2[r1], fminf(s, o));
                if (s > o) { m1[r1] = s; k1[r1] = ng; }
                s = fmaf(-0.5f, bv.y, acc[mf][nf][3]);
                o = m1[r1]; m2[r1] = fmaxf(m2[r1], fminf(s, o));
                if (s > o) { m1[r1] = s; k1[r1] = ng + 1; }
            }
        }
    }

    // merge across the 4 quad lanes (same rows, different cols)
#pragma unroll
    for (int off = 1; off <= 2; off <<= 1) {
#pragma unroll
        for (int i = 0; i < 4; i++) {
            float om1 = __shfl_xor_sync(0xFFFFFFFFu, m1[i], off);
            float om2 = __shfl_xor_sync(0xFFFFFFFFu, m2[i], off);
            int   ok  = __shfl_xor_sync(0xFFFFFFFFu, k1[i], off);
            if (om1 > m1[i]) { m2[i] = fmaxf(m1[i], om2); m1[i] = om1; k1[i] = ok; }
            else             { m2[i] = fmaxf(m2[i], om1); }
        }
    }

    __syncthreads();   // smem reuse for cross-warp reduction
    float* RM1 = (float*)smem;                 // [128][4]
    float* RM2 = (float*)(smem + 2048);
    int*   RK  = (int*)(smem + 4096);
    if ((lane & 3) == 0) {
#pragma unroll
        for (int mf = 0; mf < 2; mf++)
#pragma unroll
            for (int h = 0; h < 2; h++) {
                int ri = mf * 2 + h;
                int rl = wm * 32 + mf * 16 + h * 8 + (lane >> 2);
                RM1[rl * 4 + wn] = m1[ri];
                RM2[rl * 4 + wn] = m2[ri];
                RK [rl * 4 + wn] = k1[ri];
            }
    }
    __syncthreads();
    if (tid < M_CTA) {
        float f1 = RM1[tid * 4], f2 = RM2[tid * 4]; int fk = RK[tid * 4];
#pragma unroll
        for (int w = 1; w < 4; w++) {
            float o1 = RM1[tid * 4 + w], o2 = RM2[tid * 4 + w]; int ok = RK[tid * 4 + w];
            if (o1 > f1) { f2 = fmaxf(f1, o2); f1 = o1; fk = ok; }
            else         { f2 = fmaxf(f2, o1); }
        }
        int grow = cta * M_CTA + tid;
        g_idx[grow] = fk;
        if (f1 - f2 < EPS_GAP) { int p = atomicAdd(&g_nflag, 1); g_flagrows[p] = grow; }
    }
}

// ---------------------------------------------------------------------------
// Kernel 5: parallel fallback — grid (64 tiles, 64 row-groups), bit-exact dist
// (a2 recomputed in-block via the exact XLA shfl tree — bitwise identical)
// ---------------------------------------------------------------------------
__global__ __launch_bounds__(128)
void vq_fb_part(const float* __restrict__ z, const float* __restrict__ emb) {
    __shared__ float ec[128][68];
    __shared__ float zrow[64];
    __shared__ float b2c[128];
    __shared__ float wv[4];
    __shared__ int   wk[4];
    __shared__ float sa2;
    const int tid = threadIdx.x, t = blockIdx.x, grp = blockIdx.y;
    const int nf = g_nflag;
    if (grp >= nf) return;

    {
        const float4* g = (const float4*)(emb + (size_t)(t * 128 + tid) * D_DIM);
        float4* d = (float4*)&ec[tid][0];
#pragma unroll
        for (int i = 0; i < 16; i++) d[i] = g[i];
        b2c[tid] = g_b2[t * 128 + tid];
    }
    __syncthreads();

    for (int fi = grp; fi < nf; fi += FB_GRPS) {
        if (tid < 64) {
            int row = g_flagrows[fi];
            zrow[tid] = z[(size_t)(row >> 12) * (D_DIM * HW) + (size_t)tid * HW + (row & 4095)];
        }
        __syncthreads();
        if (tid < 32) {   // exact a2: XLA warp-tree order
            float tt = __fadd_rn(__fmul_rn(zrow[tid], zrow[tid]),
                                 __fmul_rn(zrow[tid + 32], zrow[tid + 32]));
#pragma unroll
            for (int off = 16; off >= 1; off >>= 1)
                tt = __fadd_rn(tt, __shfl_down_sync(0xFFFFFFFFu, tt, off));
            if (tid == 0) sa2 = tt;
        }
        __syncthreads();
        float acc = 0.0f;
        const float4* zb = (const float4*)&zrow[0];
        const float4* eb = (const float4*)&ec[tid][0];
#pragma unroll
        for (int i = 0; i < 16; i++) {
            float4 zv = zb[i], ev = eb[i];
            acc = fmaf(zv.x, ev.x, acc); acc = fmaf(zv.y, ev.y, acc);
            acc = fmaf(zv.z, ev.z, acc); acc = fmaf(zv.w, ev.w, acc);
        }
        float dist = __fadd_rn(__fsub_rn(sa2, __fmul_rn(2.0f, acc)), b2c[tid]);
        int   kidx = t * 128 + tid;
#pragma unroll
        for (int off = 16; off >= 1; off >>= 1) {
            float ov = __shfl_down_sync(0xFFFFFFFFu, dist, off);
            int   ok = __shfl_down_sync(0xFFFFFFFFu, kidx, off);
            if (ov < dist || (ov == dist && ok < kidx)) { dist = ov; kidx = ok; }
        }
        if ((tid & 31) == 0) { wv[tid >> 5] = dist; wk[tid >> 5] = kidx; }
        __syncthreads();
        if (tid == 0) {
            float bv = wv[0]; int bk = wk[0];
#pragma unroll
            for (int w = 1; w < 4; w++)
                if (wv[w] < bv || (wv[w] == bv && wk[w] < bk)) { bv = wv[w]; bk = wk[w]; }
            g_pval[(size_t)fi * 64 + t] = bv;
            g_pidx[(size_t)fi * 64 + t] = bk;
        }
        __syncthreads();
    }
}

// ---------------------------------------------------------------------------
// Kernel 6: fallback reduce — warp per flagged row over 64 tile results
// ---------------------------------------------------------------------------
__global__ void vq_fb_red() {
    int nf = g_nflag;
    int gw = (blockIdx.x * blockDim.x + threadIdx.x) >> 5;
    int lane = threadIdx.x & 31;
    int nwarps = (gridDim.x * blockDim.x) >> 5;
    for (int fi = gw; fi < nf; fi += nwarps) {
        float v1 = g_pval[(size_t)fi * 64 + lane];
        int   k1 = g_pidx[(size_t)fi * 64 + lane];
        float v2 = g_pval[(size_t)fi * 64 + lane + 32];
        int   k2 = g_pidx[(size_t)fi * 64 + lane + 32];
        if (v2 < v1 || (v2 == v1 && k2 < k1)) { v1 = v2; k1 = k2; }
#pragma unroll
        for (int off = 16; off >= 1; off >>= 1) {
            float ov = __shfl_down_sync(0xFFFFFFFFu, v1, off);
            int   ok = __shfl_down_sync(0xFFFFFFFFu, k1, off);
            if (ov < v1 || (ov == v1 && ok < k1)) { v1 = ov; k1 = ok; }
        }
        if (lane == 0) g_idx[g_flagrows[fi]] = k1;
    }
}

// ---------------------------------------------------------------------------
// Kernel 7: gather + STE z_q + indices + counts + loss
// ---------------------------------------------------------------------------
__global__ __launch_bounds__(256)
void vq_final(const float* __restrict__ z, const float* __restrict__ emb,
              float* __restrict__ out, int out_size) {
    const int row = blockIdx.x * 256 + threadIdx.x;
    const int b = row >> 12, hw = row & 4095;
    const int bidx = g_idx[row];
    const float* zp = z + (size_t)b * (D_DIM * HW) + hw;
    const float* eb = emb + (size_t)bidx * D_DIM;
    float* zq = out + (size_t)b * (D_DIM * HW) + hw;
    const bool wz = (out_size >= NZ);
    float ssq = 0.0f;
#pragma unroll
    for (int d = 0; d < D_DIM; d++) {
        float zv = zp[(size_t)d * HW], ev = eb[d];
        float df = __fsub_rn(zv, ev);
        ssq = fmaf(df, df, ssq);
        if (wz) zq[(size_t)d * HW] = __fadd_rn(zv, __fsub_rn(ev, zv));
    }
    if (out_size >= NZ + NI) out[NZ + row] = (float)bidx;
    atomicAdd(&g_counts[bidx], 1);
#pragma unroll
    for (int o = 16; o > 0; o >>= 1) ssq += __shfl_down_sync(0xFFFFFFFFu, ssq, o);
    if ((threadIdx.x & 31) == 0) atomicAdd(&g_loss, ssq);
}

// ---------------------------------------------------------------------------
// Kernel 8: scalars
// ---------------------------------------------------------------------------
__global__ void vq_finalize(float* __restrict__ out, int out_size) {
    __shared__ float sH[256];
    __shared__ int   sU[256];
    const int tid = threadIdx.x;
    float H = 0.0f; int used = 0;
    for (int k = tid; k < K_CODES; k += 256) {
        float c = (float)g_counts[k];
        if (c > 0.0f) used++;
        float avg = c * (1.0f / (float)N_ROWS);
        H = fmaf(avg, logf(avg + 1e-10f), H);
    }
    sH[tid] = H; sU[tid] = used;
    __syncthreads();
    for (int s = 128; s > 0; s >>= 1) {
        if (tid < s) { sH[tid] += sH[tid + s]; sU[tid] += sU[tid + s]; }
        __syncthreads();
    }
    if (tid == 0 && out_size >= NZ + NI + 3) {
        out[NZ + NI + 0] = BETA * g_loss / (float)(N_ROWS * D_DIM);
        out[NZ + NI + 1] = expf(-sH[0]);
        out[NZ + NI + 2] = (float)sU[0] / (float)K_CODES;
    }
}

// ---------------------------------------------------------------------------
extern "C" void kernel_launch(void* const* d_in, const int* in_sizes, int n_in,
                              void* d_out, int out_size) {
    const float* z   = (const float*)d_in[0];
    const float* emb = (const float*)d_in[1];
    float* out = (float*)d_out;

    cudaFuncSetAttribute(vq_gemm, cudaFuncAttributeMaxDynamicSharedMemorySize, SM_TOT);

    vq_prep_b2<<<(K_CODES * 32) / 256, 256>>>(emb);
    vq_prep_zero<<<K_CODES / 256, 256>>>();
    vq_prep_e<<<K_CODES / 256, 256>>>(emb);
    vq_gemm<<<CTAS, NTH, SM_TOT>>>(z);            // launch #4 (ncu capture slot)
    vq_fb_part<<<dim3(64, FB_GRPS), 128>>>(z, emb);
    vq_fb_red<<<64, 256>>>();
    vq_final<<<N_ROWS / 256, 256>>>(z, emb, out, out_size);
    vq_finalize<<<1, 256>>>(out, out_size);
}

// round 12
// speedup vs baseline: 1.1718x; 1.0496x over previous
#include <cuda_runtime.h>
#include <cuda_fp16.h>
#include <math.h>
#include <stdint.h>

// VanillaVQ: z_e (8,64,64,64) fp32, embedding (8192,64) fp32.
// Outputs (concat fp32): z_q | indices | commit_loss | perplexity | usage.

#define K_CODES 8192
#define D_DIM   64
#define N_ROWS  32768
#define HW      4096
#define BETA    0.25f
#define NZ (N_ROWS * D_DIM)
#define NI N_ROWS
#define EPS_GAP 3.5e-4f

// GEMM config: S = fp16(z).fp16(e) (KD=64, certified by gap test)
#define M_CTA  128
#define CTAS   256
#define NTH    512          // 16 warps: 4(M) x 4(N); warp tile 32x32
#define NT     128          // codes per chunk
#define NCH    64
#define ARS    144          // row strides (16 mod 128 -> conflict-free ldmatrix)
#define BRS    144
#define SM_A   0            // 128*144 = 18432
#define SM_B(i) (18432u + (uint32_t)(i) * 18432u)   // 3 bufs
#define SM_TOT 73728

#define FB_GRPS 64          // fallback row-groups (parallelism)

// ---------------- device scratch ----------------
__device__ float g_b2[K_CODES];
__device__ int   g_counts[K_CODES];
__device__ float g_loss;
__device__ int   g_nflag;
__device__ int   g_idx[N_ROWS];
__device__ int   g_flagrows[N_ROWS];
__device__ float g_pval[N_ROWS * 64];
__device__ int   g_pidx[N_ROWS * 64];
__device__ __align__(128) uint32_t g_E[K_CODES * 32];   // 1MB fp16 image of emb

// ---------------- helpers ----------------
__device__ __forceinline__ uint32_t smem_u32(const void* p) {
    uint32_t a;
    asm("{ .reg .u64 t; cvta.to.shared.u64 t, %1; cvt.u32.u64 %0, t; }" : "=r"(a) : "l"(p));
    return a;
}
__device__ __forceinline__ uint32_t packh(float a, float b) {
    __half2 h = __floats2half2_rn(a, b);
    return *reinterpret_cast<uint32_t*>(&h);
}
__device__ __forceinline__ void ldm_x4(uint32_t* r, uint32_t addr) {
    asm volatile("ldmatrix.sync.aligned.m8n8.x4.shared.b16 {%0,%1,%2,%3}, [%4];"
                 : "=r"(r[0]), "=r"(r[1]), "=r"(r[2]), "=r"(r[3]) : "r"(addr));
}
__device__ __forceinline__ void ldm_x2(uint32_t* r, uint32_t addr) {
    asm volatile("ldmatrix.sync.aligned.m8n8.x2.shared.b16 {%0,%1}, [%2];"
                 : "=r"(r[0]), "=r"(r[1]) : "r"(addr));
}
__device__ __forceinline__ void mma16816(float* c, const uint32_t* a, const uint32_t* b) {
    asm volatile(
        "mma.sync.aligned.m16n8k16.row.col.f32.f16.f16.f32 "
        "{%0,%1,%2,%3}, {%4,%5,%6,%7}, {%8,%9}, {%0,%1,%2,%3};"
        : "+f"(c[0]), "+f"(c[1]), "+f"(c[2]), "+f"(c[3])
        : "r"(a[0]), "r"(a[1]), "r"(a[2]), "r"(a[3]), "r"(b[0]), "r"(b[1]));
}
__device__ __forceinline__ void cp16(uint32_t dst, const void* src) {
    uint64_t gs; asm("cvta.to.global.u64 %0, %1;" : "=l"(gs) : "l"(src));
    asm volatile("cp.async.cg.shared.global [%0], [%1], 16;" :: "r"(dst), "l"(gs));
}
// top-2 insert: all lat-4 ops, no predicate-guard chains
__device__ __forceinline__ void top2(float s, int ng, float& m1, float& m2, int& k1) {
    float o = m1;
    m2 = fmaxf(m2, fminf(s, o));
    m1 = fmaxf(o, s);
    k1 = (s > o) ? ng : k1;
}

// ---------------------------------------------------------------------------
// Kernel 1: b2 in XLA warp-tree order (warp per code)
// ---------------------------------------------------------------------------
__global__ void vq_prep_b2(const float* __restrict__ emb) {
    int gtid = blockIdx.x * blockDim.x + threadIdx.x;
    int k = gtid >> 5, lane = gtid & 31;
    if (k < K_CODES) {
        const float* e = emb + (size_t)k * D_DIM;
        float t = __fadd_rn(__fmul_rn(e[lane], e[lane]),
                            __fmul_rn(e[lane + 32], e[lane + 32]));
#pragma unroll
        for (int off = 16; off >= 1; off >>= 1)
            t = __fadd_rn(t, __shfl_down_sync(0xFFFFFFFFu, t, off));
        if (lane == 0) g_b2[k] = t;
    }
}

// ---------------------------------------------------------------------------
// Kernel 2: zero accumulators
// ---------------------------------------------------------------------------
__global__ void vq_prep_zero() {
    int k = blockIdx.x * blockDim.x + threadIdx.x;
    if (k < K_CODES) g_counts[k] = 0;
    if (k == 0) { g_loss = 0.0f; g_nflag = 0; }
}

// ---------------------------------------------------------------------------
// Kernel 3: fp16 image of emb (64 fp16 per code, 128B row)
// ---------------------------------------------------------------------------
__global__ void vq_prep_e(const float* __restrict__ emb) {
    int k = blockIdx.x * blockDim.x + threadIdx.x;
    if (k >= K_CODES) return;
    uint32_t* base = g_E + (size_t)k * 32;
    const float* e = emb + (size_t)k * D_DIM;
#pragma unroll 8
    for (int j = 0; j < 32; j++)
        base[j] = packh(e[2 * j], e[2 * j + 1]);
}

// ---------------------------------------------------------------------------
// Kernel 4: fp16 HMMA GEMM  S = z.e - 0.5*b2  + running top-2 + gap flag
// 256 CTAs x 512 threads (4M x 4N warps), warp tile 32x32.
// Per-chunk loop interleaves epilogue(nf) with MMA(nf+1) to break the
// LDSM -> MMA -> epilogue phase convoy. A fragments hoisted (chunk-invariant).
// ---------------------------------------------------------------------------
__device__ __forceinline__ void copy_chunk(int c, uint32_t dstbase, int tid) {
    const char* src = (const char*)g_E + (size_t)c * (NT * 128);
#pragma unroll
    for (int t = 0; t < 2; t++) {
        int idx = tid + t * NTH;                 // 0..1023
        int row = idx >> 3, seg = idx & 7;
        cp16(dstbase + (uint32_t)row * BRS + (uint32_t)seg * 16,
             src + (size_t)row * 128 + (size_t)seg * 16);
    }
}

__global__ __launch_bounds__(NTH, 1)
void vq_gemm(const float* __restrict__ z) {
    extern __shared__ __align__(128) char smem[];
    const uint32_t sb = smem_u32(smem);
    const int tid = threadIdx.x, cta = blockIdx.x;
    const int lane = tid & 31, warp = tid >> 5;
    const int wm = warp >> 2, wn = warp & 3;      // 4(M) x 4(N)

    // ---- build A tile: row r (<128): 64 fp16 of z ----
    if (tid < M_CTA) {
        int grow = cta * M_CTA + tid;
        const float* zp = z + (size_t)(grow >> 12) * (D_DIM * HW) + (grow & 4095);
        char* ar = smem + SM_A + (size_t)tid * ARS;
#pragma unroll 8
        for (int d = 0; d < 64; d += 2)
            *(uint32_t*)(ar + 2 * d) = packh(zp[(size_t)d * HW], zp[(size_t)(d + 1) * HW]);
    }
    __syncthreads();

    // ---- hoist A fragments (chunk-invariant): 32 regs ----
    const uint32_t Abase = sb + SM_A
        + (uint32_t)(wm * 32 + (lane & 7) + ((lane >> 3) & 1) * 8) * ARS
        + ((lane >> 4) & 1) * 16;
    uint32_t afr[4][2][4];
#pragma unroll
    for (int kk = 0; kk < 4; kk++)
#pragma unroll
        for (int mf = 0; mf < 2; mf++)
            ldm_x4(afr[kk][mf], Abase + (uint32_t)mf * (16 * ARS) + (uint32_t)kk * 32);

    copy_chunk(0, sb + SM_B(0), tid);
    asm volatile("cp.async.commit_group;");
    copy_chunk(1, sb + SM_B(1), tid);
    asm volatile("cp.async.commit_group;");

    const int bl = lane & 15;
    const uint32_t Bofs = (uint32_t)(wn * 32 + (bl & 7)) * BRS + ((bl >> 3) & 1) * 16;

    float m1[4], m2[4]; int k1[4];
#pragma unroll
    for (int i = 0; i < 4; i++) { m1[i] = -3.4e38f; m2[i] = -3.4e38f; k1[i] = 0; }

    for (int c = 0; c < NCH; c++) {
        const uint32_t bbase = sb + SM_B(c % 3);
        if (c == NCH - 1) asm volatile("cp.async.wait_group 0;");
        else              asm volatile("cp.async.wait_group 1;");
        __syncthreads();     // chunk c visible; buf (c+2)%3 free
        if (c + 2 < NCH) {
            copy_chunk(c + 2, sb + SM_B((c + 2) % 3), tid);
            asm volatile("cp.async.commit_group;");
        }

#pragma unroll
        for (int nf = 0; nf < 4; nf++) {
            float a0[4] = {0.f, 0.f, 0.f, 0.f}, a1[4] = {0.f, 0.f, 0.f, 0.f};
#pragma unroll
            for (int kk = 0; kk < 4; kk++) {
                uint32_t b[2];
                ldm_x2(b, bbase + Bofs + (uint32_t)nf * (8 * BRS) + (uint32_t)kk * 32);
                mma16816(a0, afr[kk][0], b);
                mma16816(a1, afr[kk][1], b);
            }
            const int ng = c * NT + wn * 32 + nf * 8 + (lane & 3) * 2;
            const float2 bv = *(const float2*)&g_b2[ng];
            top2(fmaf(-0.5f, bv.x, a0[0]), ng,     m1[0], m2[0], k1[0]);
            top2(fmaf(-0.5f, bv.y, a0[1]), ng + 1, m1[0], m2[0], k1[0]);
            top2(fmaf(-0.5f, bv.x, a0[2]), ng,     m1[1], m2[1], k1[1]);
            top2(fmaf(-0.5f, bv.y, a0[3]), ng + 1, m1[1], m2[1], k1[1]);
            top2(fmaf(-0.5f, bv.x, a1[0]), ng,     m1[2], m2[2], k1[2]);
            top2(fmaf(-0.5f, bv.y, a1[1]), ng + 1, m1[2], m2[2], k1[2]);
            top2(fmaf(-0.5f, bv.x, a1[2]), ng,     m1[3], m2[3], k1[3]);
            top2(fmaf(-0.5f, bv.y, a1[3]), ng + 1, m1[3], m2[3], k1[3]);
        }
    }

    // merge across the 4 quad lanes (same rows, different cols)
#pragma unroll
    for (int off = 1; off <= 2; off <<= 1) {
#pragma unroll
        for (int i = 0; i < 4; i++) {
            float om1 = __shfl_xor_sync(0xFFFFFFFFu, m1[i], off);
            float om2 = __shfl_xor_sync(0xFFFFFFFFu, m2[i], off);
            int   ok  = __shfl_xor_sync(0xFFFFFFFFu, k1[i], off);
            if (om1 > m1[i]) { m2[i] = fmaxf(m1[i], om2); m1[i] = om1; k1[i] = ok; }
            else             { m2[i] = fmaxf(m2[i], om1); }
        }
    }

    __syncthreads();   // smem reuse for cross-warp reduction
    float* RM1 = (float*)smem;                 // [128][4]
    float* RM2 = (float*)(smem + 2048);
    int*   RK  = (int*)(smem + 4096);
    if ((lane & 3) == 0) {
#pragma unroll
        for (int mf = 0; mf < 2; mf++)
#pragma unroll
            for (int h = 0; h < 2; h++) {
                int ri = mf * 2 + h;
                int rl = wm * 32 + mf * 16 + h * 8 + (lane >> 2);
                RM1[rl * 4 + wn] = m1[ri];
                RM2[rl * 4 + wn] = m2[ri];
                RK [rl * 4 + wn] = k1[ri];
            }
    }
    __syncthreads();
    if (tid < M_CTA) {
        float f1 = RM1[tid * 4], f2 = RM2[tid * 4]; int fk = RK[tid * 4];
#pragma unroll
        for (int w = 1; w < 4; w++) {
            float o1 = RM1[tid * 4 + w], o2 = RM2[tid * 4 + w]; int ok = RK[tid * 4 + w];
            if (o1 > f1) { f2 = fmaxf(f1, o2); f1 = o1; fk = ok; }
            else         { f2 = fmaxf(f2, o1); }
        }
        int grow = cta * M_CTA + tid;
        g_idx[grow] = fk;
        if (f1 - f2 < EPS_GAP) { int p = atomicAdd(&g_nflag, 1); g_flagrows[p] = grow; }
    }
}

// ---------------------------------------------------------------------------
// Kernel 5: parallel fallback — grid (64 tiles, 64 row-groups), bit-exact dist
// (a2 recomputed in-block via the exact XLA shfl tree — bitwise identical)
// ---------------------------------------------------------------------------
__global__ __launch_bounds__(128)
void vq_fb_part(const float* __restrict__ z, const float* __restrict__ emb) {
    __shared__ float ec[128][68];
    __shared__ float zrow[64];
    __shared__ float b2c[128];
    __shared__ float wv[4];
    __shared__ int   wk[4];
    __shared__ float sa2;
    const int tid = threadIdx.x, t = blockIdx.x, grp = blockIdx.y;
    const int nf = g_nflag;
    if (grp >= nf) return;

    {
        const float4* g = (const float4*)(emb + (size_t)(t * 128 + tid) * D_DIM);
        float4* d = (float4*)&ec[tid][0];
#pragma unroll
        for (int i = 0; i < 16; i++) d[i] = g[i];
        b2c[tid] = g_b2[t * 128 + tid];
    }
    __syncthreads();

    for (int fi = grp; fi < nf; fi += FB_GRPS) {
        if (tid < 64) {
            int row = g_flagrows[fi];
            zrow[tid] = z[(size_t)(row >> 12) * (D_DIM * HW) + (size_t)tid * HW + (row & 4095)];
        }
        __syncthreads();
        if (tid < 32) {   // exact a2: XLA warp-tree order
            float tt = __fadd_rn(__fmul_rn(zrow[tid], zrow[tid]),
                                 __fmul_rn(zrow[tid + 32], zrow[tid + 32]));
#pragma unroll
            for (int off = 16; off >= 1; off >>= 1)
                tt = __fadd_rn(tt, __shfl_down_sync(0xFFFFFFFFu, tt, off));
            if (tid == 0) sa2 = tt;
        }
        __syncthreads();
        float acc = 0.0f;
        const float4* zb = (const float4*)&zrow[0];
        const float4* eb = (const float4*)&ec[tid][0];
#pragma unroll
        for (int i = 0; i < 16; i++) {
            float4 zv = zb[i], ev = eb[i];
            acc = fmaf(zv.x, ev.x, acc); acc = fmaf(zv.y, ev.y, acc);
            acc = fmaf(zv.z, ev.z, acc); acc = fmaf(zv.w, ev.w, acc);
        }
        float dist = __fadd_rn(__fsub_rn(sa2, __fmul_rn(2.0f, acc)), b2c[tid]);
        int   kidx = t * 128 + tid;
#pragma unroll
        for (int off = 16; off >= 1; off >>= 1) {
            float ov = __shfl_down_sync(0xFFFFFFFFu, dist, off);
            int   ok = __shfl_down_sync(0xFFFFFFFFu, kidx, off);
            if (ov < dist || (ov == dist && ok < kidx)) { dist = ov; kidx = ok; }
        }
        if ((tid & 31) == 0) { wv[tid >> 5] = dist; wk[tid >> 5] = kidx; }
        __syncthreads();
        if (tid == 0) {
            float bv = wv[0]; int bk = wk[0];
#pragma unroll
            for (int w = 1; w < 4; w++)
                if (wv[w] < bv || (wv[w] == bv && wk[w] < bk)) { bv = wv[w]; bk = wk[w]; }
            g_pval[(size_t)fi * 64 + t] = bv;
            g_pidx[(size_t)fi * 64 + t] = bk;
        }
        __syncthreads();
    }
}

// ---------------------------------------------------------------------------
// Kernel 6: fallback reduce — warp per flagged row over 64 tile results
// ---------------------------------------------------------------------------
__global__ void vq_fb_red() {
    int nf = g_nflag;
    int gw = (blockIdx.x * blockDim.x + threadIdx.x) >> 5;
    int lane = threadIdx.x & 31;
    int nwarps = (gridDim.x * blockDim.x) >> 5;
    for (int fi = gw; fi < nf; fi += nwarps) {
        float v1 = g_pval[(size_t)fi * 64 + lane];
        int   k1 = g_pidx[(size_t)fi * 64 + lane];
        float v2 = g_pval[(size_t)fi * 64 + lane + 32];
        int   k2 = g_pidx[(size_t)fi * 64 + lane + 32];
        if (v2 < v1 || (v2 == v1 && k2 < k1)) { v1 = v2; k1 = k2; }
#pragma unroll
        for (int off = 16; off >= 1; off >>= 1) {
            float ov = __shfl_down_sync(0xFFFFFFFFu, v1, off);
            int   ok = __shfl_down_sync(0xFFFFFFFFu, k1, off);
            if (ov < v1 || (ov == v1 && ok < k1)) { v1 = ov; k1 = ok; }
        }
        if (lane == 0) g_idx[g_flagrows[fi]] = k1;
    }
}

// ---------------------------------------------------------------------------
// Kernel 7: gather + STE z_q + indices + counts + loss
// ---------------------------------------------------------------------------
__global__ __launch_bounds__(256)
void vq_final(const float* __restrict__ z, const float* __restrict__ emb,
              float* __restrict__ out, int out_size) {
    const int row = blockIdx.x * 256 + threadIdx.x;
    const int b = row >> 12, hw = row & 4095;
    const int bidx = g_idx[row];
    const float* zp = z + (size_t)b * (D_DIM * HW) + hw;
    const float* eb = emb + (size_t)bidx * D_DIM;
    float* zq = out + (size_t)b * (D_DIM * HW) + hw;
    const bool wz = (out_size >= NZ);
    float ssq = 0.0f;
#pragma unroll
    for (int d = 0; d < D_DIM; d++) {
        float zv = zp[(size_t)d * HW], ev = eb[d];
        float df = __fsub_rn(zv, ev);
        ssq = fmaf(df, df, ssq);
        if (wz) zq[(size_t)d * HW] = __fadd_rn(zv, __fsub_rn(ev, zv));
    }
    if (out_size >= NZ + NI) out[NZ + row] = (float)bidx;
    atomicAdd(&g_counts[bidx], 1);
#pragma unroll
    for (int o = 16; o > 0; o >>= 1) ssq += __shfl_down_sync(0xFFFFFFFFu, ssq, o);
    if ((threadIdx.x & 31) == 0) atomicAdd(&g_loss, ssq);
}

// ---------------------------------------------------------------------------
// Kernel 8: scalars
// ---------------------------------------------------------------------------
__global__ void vq_finalize(float* __restrict__ out, int out_size) {
    __shared__ float sH[256];
    __shared__ int   sU[256];
    const int tid = threadIdx.x;
    float H = 0.0f; int used = 0;
    for (int k = tid; k < K_CODES; k += 256) {
        float c = (float)g_counts[k];
        if (c > 0.0f) used++;
        float avg = c * (1.0f / (float)N_ROWS);
        H = fmaf(avg, logf(avg + 1e-10f), H);
    }
    sH[tid] = H; sU[tid] = used;
    __syncthreads();
    for (int s = 128; s > 0; s >>= 1) {
        if (tid < s) { sH[tid] += sH[tid + s]; sU[tid] += sU[tid + s]; }
        __syncthreads();
    }
    if (tid == 0 && out_size >= NZ + NI + 3) {
        out[NZ + NI + 0] = BETA * g_loss / (float)(N_ROWS * D_DIM);
        out[NZ + NI + 1] = expf(-sH[0]);
        out[NZ + NI + 2] = (float)sU[0] / (float)K_CODES;
    }
}

// ---------------------------------------------------------------------------
extern "C" void kernel_launch(void* const* d_in, const int* in_sizes, int n_in,
                              void* d_out, int out_size) {
    const float* z   = (const float*)d_in[0];
    const float* emb = (const float*)d_in[1];
    float* out = (float*)d_out;

    cudaFuncSetAttribute(vq_gemm, cudaFuncAttributeMaxDynamicSharedMemorySize, SM_TOT);

    vq_prep_b2<<<(K_CODES * 32) / 256, 256>>>(emb);
    vq_prep_zero<<<K_CODES / 256, 256>>>();
    vq_prep_e<<<K_CODES / 256, 256>>>(emb);
    vq_gemm<<<CTAS, NTH, SM_TOT>>>(z);            // launch #4 (ncu capture slot)
    vq_fb_part<<<dim3(64, FB_GRPS), 128>>>(z, emb);
    vq_fb_red<<<64, 256>>>();
    vq_final<<<N_ROWS / 256, 256>>>(z, emb, out, out_size);
    vq_finalize<<<1, 256>>>(out, out_size);
}

// round 14
// speedup vs baseline: 1.2801x; 1.0924x over previous
#include <cuda_runtime.h>
#include <cuda_fp16.h>
#include <math.h>
#include <stdint.h>

// VanillaVQ: z_e (8,64,64,64) fp32, embedding (8192,64) fp32.
// Outputs (concat fp32): z_q | indices | commit_loss | perplexity | usage.

#define K_CODES 8192
#define D_DIM   64
#define N_ROWS  32768
#define HW      4096
#define BETA    0.25f
#define NZ (N_ROWS * D_DIM)
#define NI N_ROWS
#define EPS_GAP 3.5e-4f

// GEMM config: S = fp16(z).fp16(e) (KD=64, certified by gap test)
#define M_CTA  128
#define CTAS   256
#define NTH    512          // 16 warps: 4(M) x 4(N); warp tile 32x64
#define NT     256          // codes per chunk
#define NCH    32
#define ARS    144          // row strides (16 mod 128 -> conflict-free ldmatrix)
#define BRS    144
#define SM_A   0                                     // 128*144 = 18432
#define SM_B(i) (18432u + (uint32_t)(i) * 36864u)    // 3 bufs of 256*144
#define SM_B2  129024u                               // 32KB b2 copy
#define SM_TOT 161792

#define FB_GRPS 64          // fallback row-groups (parallelism)

// ---------------- device scratch ----------------
__device__ float g_b2[K_CODES];
__device__ int   g_counts[K_CODES];
__device__ float g_loss;
__device__ int   g_nflag;
__device__ int   g_idx[N_ROWS];
__device__ int   g_flagrows[N_ROWS];
__device__ float g_pval[N_ROWS * 64];
__device__ int   g_pidx[N_ROWS * 64];
__device__ __align__(128) uint32_t g_E[K_CODES * 32];   // 1MB fp16 image of emb

// ---------------- helpers ----------------
__device__ __forceinline__ uint32_t smem_u32(const void* p) {
    uint32_t a;
    asm("{ .reg .u64 t; cvta.to.shared.u64 t, %1; cvt.u32.u64 %0, t; }" : "=r"(a) : "l"(p));
    return a;
}
__device__ __forceinline__ uint32_t packh(float a, float b) {
    __half2 h = __floats2half2_rn(a, b);
    return *reinterpret_cast<uint32_t*>(&h);
}
__device__ __forceinline__ void ldm_x4(uint32_t* r, uint32_t addr) {
    asm volatile("ldmatrix.sync.aligned.m8n8.x4.shared.b16 {%0,%1,%2,%3}, [%4];"
                 : "=r"(r[0]), "=r"(r[1]), "=r"(r[2]), "=r"(r[3]) : "r"(addr));
}
__device__ __forceinline__ void ldm_x2(uint32_t* r, uint32_t addr) {
    asm volatile("ldmatrix.sync.aligned.m8n8.x2.shared.b16 {%0,%1}, [%2];"
                 : "=r"(r[0]), "=r"(r[1]) : "r"(addr));
}
__device__ __forceinline__ void mma16816(float* c, const uint32_t* a, const uint32_t* b) {
    asm volatile(
        "mma.sync.aligned.m16n8k16.row.col.f32.f16.f16.f32 "
        "{%0,%1,%2,%3}, {%4,%5,%6,%7}, {%8,%9}, {%0,%1,%2,%3};"
        : "+f"(c[0]), "+f"(c[1]), "+f"(c[2]), "+f"(c[3])
        : "r"(a[0]), "r"(a[1]), "r"(a[2]), "r"(a[3]), "r"(b[0]), "r"(b[1]));
}
__device__ __forceinline__ void cp16(uint32_t dst, const void* src) {
    uint64_t gs; asm("cvta.to.global.u64 %0, %1;" : "=l"(gs) : "l"(src));
    asm volatile("cp.async.cg.shared.global [%0], [%1], 16;" :: "r"(dst), "l"(gs));
}
// pack 9-bit id into low mantissa bits: one LOP3. Order-preserving above the
// 2^9-ulp quantum; any within-quantum ambiguity makes gap<EPS -> flagged ->
// resolved by the bit-exact fallback.
__device__ __forceinline__ float packid(float s, int idx) {
    return __int_as_float((__float_as_int(s) & ~0x1FF) | idx);
}
// packed top-2: pure FMNMX, no predicate chains, no index registers
__device__ __forceinline__ void top2p(float p, float& m1, float& m2) {
    m2 = fmaxf(m2, fminf(p, m1));
    m1 = fmaxf(m1, p);
}

// ---------------------------------------------------------------------------
// Kernel 1: b2 in XLA warp-tree order (warp per code)
// ---------------------------------------------------------------------------
__global__ void vq_prep_b2(const float* __restrict__ emb) {
    int gtid = blockIdx.x * blockDim.x + threadIdx.x;
    int k = gtid >> 5, lane = gtid & 31;
    if (k < K_CODES) {
        const float* e = emb + (size_t)k * D_DIM;
        float t = __fadd_rn(__fmul_rn(e[lane], e[lane]),
                            __fmul_rn(e[lane + 32], e[lane + 32]));
#pragma unroll
        for (int off = 16; off >= 1; off >>= 1)
            t = __fadd_rn(t, __shfl_down_sync(0xFFFFFFFFu, t, off));
        if (lane == 0) g_b2[k] = t;
    }
}

// ---------------------------------------------------------------------------
// Kernel 2: zero accumulators
// ---------------------------------------------------------------------------
__global__ void vq_prep_zero() {
    int k = blockIdx.x * blockDim.x + threadIdx.x;
    if (k < K_CODES) g_counts[k] = 0;
    if (k == 0) { g_loss = 0.0f; g_nflag = 0; }
}

// ---------------------------------------------------------------------------
// Kernel 3: fp16 image of emb (64 fp16 per code, 128B row)
// ---------------------------------------------------------------------------
__global__ void vq_prep_e(const float* __restrict__ emb) {
    int k = blockIdx.x * blockDim.x + threadIdx.x;
    if (k >= K_CODES) return;
    uint32_t* base = g_E + (size_t)k * 32;
    const float* e = emb + (size_t)k * D_DIM;
#pragma unroll 8
    for (int j = 0; j < 32; j++)
        base[j] = packh(e[2 * j], e[2 * j + 1]);
}

// ---------------------------------------------------------------------------
// Kernel 4: fp16 HMMA GEMM  S = z.e - 0.5*b2  + packed-index top-2 + gap flag
// 256 CTAs x 512 threads (4M x 4N warps). NT=256 codes/chunk, NCH=32.
// b2 staged in smem (chunk-offset FIXED); ids packed into mantissa.
// ---------------------------------------------------------------------------
__device__ __forceinline__ void copy_chunk(int c, uint32_t dstbase, int tid) {
    const char* src = (const char*)g_E + (size_t)c * (NT * 128);
#pragma unroll
    for (int t = 0; t < 4; t++) {
        int idx = tid + t * NTH;                 // 0..2047
        int row = idx >> 3, seg = idx & 7;
        cp16(dstbase + (uint32_t)row * BRS + (uint32_t)seg * 16,
             src + (size_t)row * 128 + (size_t)seg * 16);
    }
}

__global__ __launch_bounds__(NTH, 1)
void vq_gemm(const float* __restrict__ z) {
    extern __shared__ __align__(128) char smem[];
    const uint32_t sb = smem_u32(smem);
    const int tid = threadIdx.x, cta = blockIdx.x;
    const int lane = tid & 31, warp = tid >> 5;
    const int wm = warp >> 2, wn = warp & 3;      // 4(M) x 4(N)

    // ---- build A tile: row r (<128): 64 fp16 of z ----
    if (tid < M_CTA) {
        int grow = cta * M_CTA + tid;
        const float* zp = z + (size_t)(grow >> 12) * (D_DIM * HW) + (grow & 4095);
        char* ar = smem + SM_A + (size_t)tid * ARS;
#pragma unroll 8
        for (int d = 0; d < 64; d += 2)
            *(uint32_t*)(ar + 2 * d) = packh(zp[(size_t)d * HW], zp[(size_t)(d + 1) * HW]);
    }
    __syncthreads();

    // ---- hoist A fragments (chunk-invariant): 32 regs ----
    const uint32_t Abase = sb + SM_A
        + (uint32_t)(wm * 32 + (lane & 7) + ((lane >> 3) & 1) * 8) * ARS
        + ((lane >> 4) & 1) * 16;
    uint32_t afr[4][2][4];
#pragma unroll
    for (int kk = 0; kk < 4; kk++)
#pragma unroll
        for (int mf = 0; mf < 2; mf++)
            ldm_x4(afr[kk][mf], Abase + (uint32_t)mf * (16 * ARS) + (uint32_t)kk * 32);

    // b2 -> smem (32KB) grouped with chunk 0
    {
        const char* bsrc = (const char*)g_b2;
#pragma unroll
        for (int t = 0; t < 4; t++) {
            int idx = tid + t * NTH;
            cp16(sb + SM_B2 + (uint32_t)idx * 16, bsrc + (size_t)idx * 16);
        }
    }
    copy_chunk(0, sb + SM_B(0), tid);
    asm volatile("cp.async.commit_group;");
    copy_chunk(1, sb + SM_B(1), tid);
    asm volatile("cp.async.commit_group;");

    const int bl = lane & 15;
    const uint32_t Bofs = (uint32_t)(wn * 64 + (bl & 7)) * BRS + ((bl >> 3) & 1) * 16;
    const uint32_t b2off = SM_B2 + (uint32_t)(wn * 64 + (lane & 3) * 2) * 4;

    float m1[4], m2[4];
#pragma unroll
    for (int i = 0; i < 4; i++) { m1[i] = -3.4e38f; m2[i] = -3.4e38f; }

    for (int c = 0; c < NCH; c++) {
        const uint32_t bbase = sb + SM_B(c % 3);
        if (c == NCH - 1) asm volatile("cp.async.wait_group 0;");
        else              asm volatile("cp.async.wait_group 1;");
        __syncthreads();     // chunk c visible; buf (c+2)%3 free
        if (c + 2 < NCH) {
            copy_chunk(c + 2, sb + SM_B((c + 2) % 3), tid);
            asm volatile("cp.async.commit_group;");
        }
        const int cbase = c << 4;
        // chunk-local b2 slice (FIX: offset by c*NT floats)
        const char* b2p = smem + b2off + (uint32_t)c * (NT * 4);

#pragma unroll
        for (int nf = 0; nf < 8; nf++) {
            float a0[4] = {0.f, 0.f, 0.f, 0.f}, a1[4] = {0.f, 0.f, 0.f, 0.f};
#pragma unroll
            for (int kk = 0; kk < 4; kk++) {
                uint32_t b[2];
                ldm_x2(b, bbase + Bofs + (uint32_t)nf * (8 * BRS) + (uint32_t)kk * 32);
                mma16816(a0, afr[kk][0], b);
                mma16816(a1, afr[kk][1], b);
            }
            float2 bv = *(const float2*)(b2p + (size_t)nf * 32);
            const int idx0 = cbase | (nf << 1), idx1 = idx0 | 1;
            top2p(packid(fmaf(-0.5f, bv.x, a0[0]), idx0), m1[0], m2[0]);
            top2p(packid(fmaf(-0.5f, bv.y, a0[1]), idx1), m1[0], m2[0]);
            top2p(packid(fmaf(-0.5f, bv.x, a0[2]), idx0), m1[1], m2[1]);
            top2p(packid(fmaf(-0.5f, bv.y, a0[3]), idx1), m1[1], m2[1]);
            top2p(packid(fmaf(-0.5f, bv.x, a1[0]), idx0), m1[2], m2[2]);
            top2p(packid(fmaf(-0.5f, bv.y, a1[1]), idx1), m1[2], m2[2]);
            top2p(packid(fmaf(-0.5f, bv.x, a1[2]), idx0), m1[3], m2[3]);
            top2p(packid(fmaf(-0.5f, bv.y, a1[3]), idx1), m1[3], m2[3]);
        }
    }

    // decode per-lane indices (before quad merge: uses this lane's (lane&3))
    int k1[4];
#pragma unroll
    for (int i = 0; i < 4; i++) {
        int bits = __float_as_int(m1[i]) & 0x1FF;
        k1[i] = (bits >> 4) * NT + wn * 64 + (((bits >> 1) & 7) << 3)
              + (lane & 3) * 2 + (bits & 1);
    }

    // merge across the 4 quad lanes (same rows, different cols)
#pragma unroll
    for (int off = 1; off <= 2; off <<= 1) {
#pragma unroll
        for (int i = 0; i < 4; i++) {
            float om1 = __shfl_xor_sync(0xFFFFFFFFu, m1[i], off);
            float om2 = __shfl_xor_sync(0xFFFFFFFFu, m2[i], off);
            int   ok  = __shfl_xor_sync(0xFFFFFFFFu, k1[i], off);
            if (om1 > m1[i]) { m2[i] = fmaxf(m1[i], om2); m1[i] = om1; k1[i] = ok; }
            else             { m2[i] = fmaxf(m2[i], om1); }
        }
    }

    __syncthreads();   // smem reuse for cross-warp reduction
    float* RM1 = (float*)smem;                 // [128][4]
    float* RM2 = (float*)(smem + 2048);
    int*   RK  = (int*)(smem + 4096);
    if ((lane & 3) == 0) {
#pragma unroll
        for (int mf = 0; mf < 2; mf++)
#pragma unroll
            for (int h = 0; h < 2; h++) {
                int ri = mf * 2 + h;
                int rl = wm * 32 + mf * 16 + h * 8 + (lane >> 2);
                RM1[rl * 4 + wn] = m1[ri];
                RM2[rl * 4 + wn] = m2[ri];
                RK [rl * 4 + wn] = k1[ri];
            }
    }
    __syncthreads();
    if (tid < M_CTA) {
        float f1 = RM1[tid * 4], f2 = RM2[tid * 4]; int fk = RK[tid * 4];
#pragma unroll
        for (int w = 1; w < 4; w++) {
            float o1 = RM1[tid * 4 + w], o2 = RM2[tid * 4 + w]; int ok = RK[tid * 4 + w];
            if (o1 > f1) { f2 = fmaxf(f1, o2); f1 = o1; fk = ok; }
            else         { f2 = fmaxf(f2, o1); }
        }
        int grow = cta * M_CTA + tid;
        g_idx[grow] = fk;
        if (f1 - f2 < EPS_GAP) { int p = atomicAdd(&g_nflag, 1); g_flagrows[p] = grow; }
    }
}

// ---------------------------------------------------------------------------
// Kernel 5: parallel fallback — grid (64 tiles, 64 row-groups), bit-exact dist
// ---------------------------------------------------------------------------
__global__ __launch_bounds__(128)
void vq_fb_part(const float* __restrict__ z, const float* __restrict__ emb) {
    __shared__ float ec[128][68];
    __shared__ float zrow[64];
    __shared__ float b2c[128];
    __shared__ float wv[4];
    __shared__ int   wk[4];
    __shared__ float sa2;
    const int tid = threadIdx.x, t = blockIdx.x, grp = blockIdx.y;
    const int nf = g_nflag;
    if (grp >= nf) return;

    {
        const float4* g = (const float4*)(emb + (size_t)(t * 128 + tid) * D_DIM);
        float4* d = (float4*)&ec[tid][0];
#pragma unroll
        for (int i = 0; i < 16; i++) d[i] = g[i];
        b2c[tid] = g_b2[t * 128 + tid];
    }
    __syncthreads();

    for (int fi = grp; fi < nf; fi += FB_GRPS) {
        if (tid < 64) {
            int row = g_flagrows[fi];
            zrow[tid] = z[(size_t)(row >> 12) * (D_DIM * HW) + (size_t)tid * HW + (row & 4095)];
        }
        __syncthreads();
        if (tid < 32) {   // exact a2: XLA warp-tree order
            float tt = __fadd_rn(__fmul_rn(zrow[tid], zrow[tid]),
                                 __fmul_rn(zrow[tid + 32], zrow[tid + 32]));
#pragma unroll
            for (int off = 16; off >= 1; off >>= 1)
                tt = __fadd_rn(tt, __shfl_down_sync(0xFFFFFFFFu, tt, off));
            if (tid == 0) sa2 = tt;
        }
        __syncthreads();
        float acc = 0.0f;
        const float4* zb = (const float4*)&zrow[0];
        const float4* eb = (const float4*)&ec[tid][0];
#pragma unroll
        for (int i = 0; i < 16; i++) {
            float4 zv = zb[i], ev = eb[i];
            acc = fmaf(zv.x, ev.x, acc); acc = fmaf(zv.y, ev.y, acc);
            acc = fmaf(zv.z, ev.z, acc); acc = fmaf(zv.w, ev.w, acc);
        }
        float dist = __fadd_rn(__fsub_rn(sa2, __fmul_rn(2.0f, acc)), b2c[tid]);
        int   kidx = t * 128 + tid;
#pragma unroll
        for (int off = 16; off >= 1; off >>= 1) {
            float ov = __shfl_down_sync(0xFFFFFFFFu, dist, off);
            int   ok = __shfl_down_sync(0xFFFFFFFFu, kidx, off);
            if (ov < dist || (ov == dist && ok < kidx)) { dist = ov; kidx = ok; }
        }
        if ((tid & 31) == 0) { wv[tid >> 5] = dist; wk[tid >> 5] = kidx; }
        __syncthreads();
        if (tid == 0) {
            float bv = wv[0]; int bk = wk[0];
#pragma unroll
            for (int w = 1; w < 4; w++)
                if (wv[w] < bv || (wv[w] == bv && wk[w] < bk)) { bv = wv[w]; bk = wk[w]; }
            g_pval[(size_t)fi * 64 + t] = bv;
            g_pidx[(size_t)fi * 64 + t] = bk;
        }
        __syncthreads();
    }
}

// ---------------------------------------------------------------------------
// Kernel 6: fallback reduce — warp per flagged row over 64 tile results
// ---------------------------------------------------------------------------
__global__ void vq_fb_red() {
    int nf = g_nflag;
    int gw = (blockIdx.x * blockDim.x + threadIdx.x) >> 5;
    int lane = threadIdx.x & 31;
    int nwarps = (gridDim.x * blockDim.x) >> 5;
    for (int fi = gw; fi < nf; fi += nwarps) {
        float v1 = g_pval[(size_t)fi * 64 + lane];
        int   k1 = g_pidx[(size_t)fi * 64 + lane];
        float v2 = g_pval[(size_t)fi * 64 + lane + 32];
        int   k2 = g_pidx[(size_t)fi * 64 + lane + 32];
        if (v2 < v1 || (v2 == v1 && k2 < k1)) { v1 = v2; k1 = k2; }
#pragma unroll
        for (int off = 16; off >= 1; off >>= 1) {
            float ov = __shfl_down_sync(0xFFFFFFFFu, v1, off);
            int   ok = __shfl_down_sync(0xFFFFFFFFu, k1, off);
            if (ov < v1 || (ov == v1 && ok < k1)) { v1 = ov; k1 = ok; }
        }
        if (lane == 0) g_idx[g_flagrows[fi]] = k1;
    }
}

// ---------------------------------------------------------------------------
// Kernel 7: gather + STE z_q + indices + counts + loss
// ---------------------------------------------------------------------------
__global__ __launch_bounds__(256)
void vq_final(const float* __restrict__ z, const float* __restrict__ emb,
              float* __restrict__ out, int out_size) {
    const int row = blockIdx.x * 256 + threadIdx.x;
    const int b = row >> 12, hw = row & 4095;
    const int bidx = g_idx[row];
    const float* zp = z + (size_t)b * (D_DIM * HW) + hw;
    const float* eb = emb + (size_t)bidx * D_DIM;
    float* zq = out + (size_t)b * (D_DIM * HW) + hw;
    const bool wz = (out_size >= NZ);
    float ssq = 0.0f;
#pragma unroll
    for (int d = 0; d < D_DIM; d++) {
        float zv = zp[(size_t)d * HW], ev = eb[d];
        float df = __fsub_rn(zv, ev);
        ssq = fmaf(df, df, ssq);
        if (wz) zq[(size_t)d * HW] = __fadd_rn(zv, __fsub_rn(ev, zv));
    }
    if (out_size >= NZ + NI) out[NZ + row] = (float)bidx;
    atomicAdd(&g_counts[bidx], 1);
#pragma unroll
    for (int o = 16; o > 0; o >>= 1) ssq += __shfl_down_sync(0xFFFFFFFFu, ssq, o);
    if ((threadIdx.x & 31) == 0) atomicAdd(&g_loss, ssq);
}

// ---------------------------------------------------------------------------
// Kernel 8: scalars
// ---------------------------------------------------------------------------
__global__ void vq_finalize(float* __restrict__ out, int out_size) {
    __shared__ float sH[256];
    __shared__ int   sU[256];
    const int tid = threadIdx.x;
    float H = 0.0f; int used = 0;
    for (int k = tid; k < K_CODES; k += 256) {
        float c = (float)g_counts[k];
        if (c > 0.0f) used++;
        float avg = c * (1.0f / (float)N_ROWS);
        H = fmaf(avg, logf(avg + 1e-10f), H);
    }
    sH[tid] = H; sU[tid] = used;
    __syncthreads();
    for (int s = 128; s > 0; s >>= 1) {
        if (tid < s) { sH[tid] += sH[tid + s]; sU[tid] += sU[tid + s]; }
        __syncthreads();
    }
    if (tid == 0 && out_size >= NZ + NI + 3) {
        out[NZ + NI + 0] = BETA * g_loss / (float)(N_ROWS * D_DIM);
        out[NZ + NI + 1] = expf(-sH[0]);
        out[NZ + NI + 2] = (float)sU[0] / (float)K_CODES;
    }
}

// ---------------------------------------------------------------------------
extern "C" void kernel_launch(void* const* d_in, const int* in_sizes, int n_in,
                              void* d_out, int out_size) {
    const float* z   = (const float*)d_in[0];
    const float* emb = (const float*)d_in[1];
    float* out = (float*)d_out;

    cudaFuncSetAttribute(vq_gemm, cudaFuncAttributeMaxDynamicSharedMemorySize, SM_TOT);

    vq_prep_b2<<<(K_CODES * 32) / 256, 256>>>(emb);
    vq_prep_zero<<<K_CODES / 256, 256>>>();
    vq_prep_e<<<K_CODES / 256, 256>>>(emb);
    vq_gemm<<<CTAS, NTH, SM_TOT>>>(z);            // launch #4 (ncu capture slot)
    vq_fb_part<<<dim3(64, FB_GRPS), 128>>>(z, emb);
    vq_fb_red<<<64, 256>>>();
    vq_final<<<N_ROWS / 256, 256>>>(z, emb, out, out_size);
    vq_finalize<<<1, 256>>>(out, out_size);
}

// round 15
// speedup vs baseline: 1.3235x; 1.0340x over previous
#include <cuda_runtime.h>
#include <cuda_fp16.h>
#include <math.h>
#include <stdint.h>

// VanillaVQ: z_e (8,64,64,64) fp32, embedding (8192,64) fp32.
// Outputs (concat fp32): z_q | indices | commit_loss | perplexity | usage.

#define K_CODES 8192
#define D_DIM   64
#define N_ROWS  32768
#define HW      4096
#define BETA    0.25f
#define NZ (N_ROWS * D_DIM)
#define NI N_ROWS
#define EPS_GAP 3.5e-4f

// GEMM: S = fp16(z).fp16(e) - 0.5*b2, bias folded in as K-extension (KD=80)
#define M_CTA  128
#define CTAS   256
#define NTH    512          // 16 warps: 4(M) x 4(N); warp tile 32x64
#define NT     256          // codes per chunk
#define NCH    32
#define KROW   40           // u32 per B row in gmem (80 fp16 = 160B)
#define ARS    176          // smem row strides (176/16=11, odd -> conflict-free)
#define BRS    176
#define SM_A   0                                     // 128*176 = 22528
#define SM_B(i) (22528u + (uint32_t)(i) * 45056u)    // 3 bufs of 256*176
#define SM_TOT 157696

#define FB_GRPS 64          // fallback row-groups (parallelism)

// ---------------- device scratch ----------------
__device__ float g_b2[K_CODES];
__device__ int   g_counts[K_CODES];
__device__ float g_loss;
__device__ int   g_nflag;
__device__ int   g_idx[N_ROWS];
__device__ int   g_flagrows[N_ROWS];
__device__ float g_pval[N_ROWS * 64];
__device__ int   g_pidx[N_ROWS * 64];
__device__ __align__(128) uint32_t g_E[K_CODES * KROW];   // 1.25MB fp16 image+bias

// ---------------- helpers ----------------
__device__ __forceinline__ uint32_t smem_u32(const void* p) {
    uint32_t a;
    asm("{ .reg .u64 t; cvta.to.shared.u64 t, %1; cvt.u32.u64 %0, t; }" : "=r"(a) : "l"(p));
    return a;
}
__device__ __forceinline__ uint32_t packh(float a, float b) {
    __half2 h = __floats2half2_rn(a, b);
    return *reinterpret_cast<uint32_t*>(&h);
}
__device__ __forceinline__ void ldm_x4(uint32_t* r, uint32_t addr) {
    asm volatile("ldmatrix.sync.aligned.m8n8.x4.shared.b16 {%0,%1,%2,%3}, [%4];"
                 : "=r"(r[0]), "=r"(r[1]), "=r"(r[2]), "=r"(r[3]) : "r"(addr));
}
__device__ __forceinline__ void ldm_x2(uint32_t* r, uint32_t addr) {
    asm volatile("ldmatrix.sync.aligned.m8n8.x2.shared.b16 {%0,%1}, [%2];"
                 : "=r"(r[0]), "=r"(r[1]) : "r"(addr));
}
__device__ __forceinline__ void mma16816(float* c, const uint32_t* a, const uint32_t* b) {
    asm volatile(
        "mma.sync.aligned.m16n8k16.row.col.f32.f16.f16.f32 "
        "{%0,%1,%2,%3}, {%4,%5,%6,%7}, {%8,%9}, {%0,%1,%2,%3};"
        : "+f"(c[0]), "+f"(c[1]), "+f"(c[2]), "+f"(c[3])
        : "r"(a[0]), "r"(a[1]), "r"(a[2]), "r"(a[3]), "r"(b[0]), "r"(b[1]));
}
__device__ __forceinline__ void cp16(uint32_t dst, const void* src) {
    uint64_t gs; asm("cvta.to.global.u64 %0, %1;" : "=l"(gs) : "l"(src));
    asm volatile("cp.async.cg.shared.global [%0], [%1], 16;" :: "r"(dst), "l"(gs));
}
// pack 9-bit id into low mantissa bits (one LOP3); within-quantum ambiguity
// implies gap<EPS -> flagged -> bit-exact fallback decides.
__device__ __forceinline__ float packid(float s, int idx) {
    return __int_as_float((__float_as_int(s) & ~0x1FF) | idx);
}
// packed top-2: pure FMNMX
__device__ __forceinline__ void top2p(float p, float& m1, float& m2) {
    m2 = fmaxf(m2, fminf(p, m1));
    m1 = fmaxf(m1, p);
}

// ---------------------------------------------------------------------------
// Kernel 1 (merged prep): warp per code — b2 (XLA tree order), fp16 image row
// [e | -0.5*b2 | zeros], zero counters.
// ---------------------------------------------------------------------------
__global__ void vq_prep(const float* __restrict__ emb) {
    int gtid = blockIdx.x * blockDim.x + threadIdx.x;
    int k = gtid >> 5, lane = gtid & 31;
    if (k < K_CODES) {
        const float* e = emb + (size_t)k * D_DIM;
        float t = __fadd_rn(__fmul_rn(e[lane], e[lane]),
                            __fmul_rn(e[lane + 32], e[lane + 32]));
#pragma unroll
        for (int off = 16; off >= 1; off >>= 1)
            t = __fadd_rn(t, __shfl_down_sync(0xFFFFFFFFu, t, off));
        uint32_t* row = g_E + (size_t)k * KROW;
        row[lane] = packh(e[2 * lane], e[2 * lane + 1]);   // dims 0..63
        if (lane < 8)
            row[32 + lane] = (lane == 0) ? packh(-0.5f * t, 0.0f) : 0u;  // dim 64 bias
        if (lane == 0) { g_b2[k] = t; g_counts[k] = 0; }
    }
    if (gtid == 0) { g_loss = 0.0f; g_nflag = 0; }
}

// ---------------------------------------------------------------------------
// Kernel 2: fp16 HMMA GEMM (KD=80, bias in-GEMM) + pipelined epilogue
// 256 CTAs x 512 threads (4M x 4N warps), warp tile 32x64, NT=256, NCH=32.
// ---------------------------------------------------------------------------
__device__ __forceinline__ void copy_chunk(int c, uint32_t dstbase, int tid) {
    const char* src = (const char*)g_E + (size_t)c * (NT * 160);
#pragma unroll
    for (int t = 0; t < 5; t++) {
        int idx = tid + t * NTH;                 // 0..2559
        int row = idx / 10, seg = idx % 10;
        cp16(dstbase + (uint32_t)row * BRS + (uint32_t)seg * 16,
             src + (size_t)row * 160 + (size_t)seg * 16);
    }
}

__global__ __launch_bounds__(NTH, 1)
void vq_gemm(const float* __restrict__ z) {
    extern __shared__ __align__(128) char smem[];
    const uint32_t sb = smem_u32(smem);
    const int tid = threadIdx.x, cta = blockIdx.x;
    const int lane = tid & 31, warp = tid >> 5;
    const int wm = warp >> 2, wn = warp & 3;      // 4(M) x 4(N)

    // ---- build A tile: row r (<128): [64 fp16 z | 1.0 | zeros] ----
    if (tid < M_CTA) {
        int grow = cta * M_CTA + tid;
        const float* zp = z + (size_t)(grow >> 12) * (D_DIM * HW) + (grow & 4095);
        char* ar = smem + SM_A + (size_t)tid * ARS;
#pragma unroll 8
        for (int d = 0; d < 64; d += 2)
            *(uint32_t*)(ar + 2 * d) = packh(zp[(size_t)d * HW], zp[(size_t)(d + 1) * HW]);
        *(uint32_t*)(ar + 128) = packh(1.0f, 0.0f);
#pragma unroll
        for (int j = 33; j < 44; j++)            // dims 66..87 incl. pad
            *(uint32_t*)(ar + 4 * j) = 0u;
    }
    __syncthreads();

    // ---- hoist A fragments (kernel-invariant): 5 ksteps x 2 mf x 4 = 40 regs ----
    const uint32_t Abase = sb + SM_A
        + (uint32_t)(wm * 32 + (lane & 7) + ((lane >> 3) & 1) * 8) * ARS
        + ((lane >> 4) & 1) * 16;
    uint32_t afr[5][2][4];
#pragma unroll
    for (int kk = 0; kk < 5; kk++)
#pragma unroll
        for (int mf = 0; mf < 2; mf++)
            ldm_x4(afr[kk][mf], Abase + (uint32_t)mf * (16 * ARS) + (uint32_t)kk * 32);

    copy_chunk(0, sb + SM_B(0), tid);
    asm volatile("cp.async.commit_group;");
    copy_chunk(1, sb + SM_B(1), tid);
    asm volatile("cp.async.commit_group;");

    // B lane addressing: x4 pairs two k-steps (lanes 16-31 at +32B)
    const uint32_t Brow0 = (uint32_t)(wn * 64 + (lane & 7)) * BRS
                         + ((lane >> 3) & 1) * 16 + ((lane >> 4) & 1) * 32;

    float m1[4], m2[4];
#pragma unroll
    for (int i = 0; i < 4; i++) { m1[i] = -3.4e38f; m2[i] = -3.4e38f; }

    float acc[2][2][4];    // ping-pong [parity][mf][v]

#define EPILOG(P, IDXBASE) do {                                           \
    const int _i0 = (IDXBASE), _i1 = (IDXBASE) | 1;                       \
    top2p(packid(acc[P][0][0], _i0), m1[0], m2[0]);                       \
    top2p(packid(acc[P][0][1], _i1), m1[0], m2[0]);                       \
    top2p(packid(acc[P][0][2], _i0), m1[1], m2[1]);                       \
    top2p(packid(acc[P][0][3], _i1), m1[1], m2[1]);                       \
    top2p(packid(acc[P][1][0], _i0), m1[2], m2[2]);                       \
    top2p(packid(acc[P][1][1], _i1), m1[2], m2[2]);                       \
    top2p(packid(acc[P][1][2], _i0), m1[3], m2[3]);                       \
    top2p(packid(acc[P][1][3], _i1), m1[3], m2[3]);                       \
} while (0)

    for (int c = 0; c < NCH; c++) {
        const uint32_t bbase = sb + SM_B(c % 3);
        if (c == NCH - 1) asm volatile("cp.async.wait_group 0;");
        else              asm volatile("cp.async.wait_group 1;");
        __syncthreads();     // chunk c visible; buf (c+2)%3 free
        if (c + 2 < NCH) {
            copy_chunk(c + 2, sb + SM_B((c + 2) % 3), tid);
            asm volatile("cp.async.commit_group;");
        }
        const int cbase = c << 4;

#pragma unroll
        for (int nf = 0; nf < 8; nf++) {
            const int p = nf & 1;
            float* a0 = acc[p][0];
            float* a1 = acc[p][1];
#pragma unroll
            for (int v = 0; v < 4; v++) { a0[v] = 0.0f; a1[v] = 0.0f; }

            const uint32_t brow = bbase + Brow0 + (uint32_t)nf * (8 * BRS);
            uint32_t b4[4], b2f[2];
            ldm_x4(b4, brow);                       // ksteps 0,1
            mma16816(a0, afr[0][0], &b4[0]); mma16816(a1, afr[0][1], &b4[0]);
            mma16816(a0, afr[1][0], &b4[2]); mma16816(a1, afr[1][1], &b4[2]);
            ldm_x4(b4, brow + 64);                  // ksteps 2,3
            mma16816(a0, afr[2][0], &b4[0]); mma16816(a1, afr[2][1], &b4[0]);
            mma16816(a0, afr[3][0], &b4[2]); mma16816(a1, afr[3][1], &b4[2]);
            ldm_x2(b2f, brow + 128);                // kstep 4 (bias column)
            mma16816(a0, afr[4][0], b2f);  mma16816(a1, afr[4][1], b2f);

            if (nf > 0) EPILOG(1 - p, cbase | ((nf - 1) << 1));
        }
        EPILOG(1, cbase | (7 << 1));   // tail: nf=7 (parity 1)
    }
#undef EPILOG

    // decode per-lane indices (before quad merge: uses this lane's (lane&3))
    int k1[4];
#pragma unroll
    for (int i = 0; i < 4; i++) {
        int bits = __float_as_int(m1[i]) & 0x1FF;
        k1[i] = (bits >> 4) * NT + wn * 64 + (((bits >> 1) & 7) << 3)
              + (lane & 3) * 2 + (bits & 1);
    }

    // merge across the 4 quad lanes (same rows, different cols)
#pragma unroll
    for (int off = 1; off <= 2; off <<= 1) {
#pragma unroll
        for (int i = 0; i < 4; i++) {
            float om1 = __shfl_xor_sync(0xFFFFFFFFu, m1[i], off);
            float om2 = __shfl_xor_sync(0xFFFFFFFFu, m2[i], off);
            int   ok  = __shfl_xor_sync(0xFFFFFFFFu, k1[i], off);
            if (om1 > m1[i]) { m2[i] = fmaxf(m1[i], om2); m1[i] = om1; k1[i] = ok; }
            else             { m2[i] = fmaxf(m2[i], om1); }
        }
    }

    __syncthreads();   // smem reuse for cross-warp reduction
    float* RM1 = (float*)smem;                 // [128][4]
    float* RM2 = (float*)(smem + 2048);
    int*   RK  = (int*)(smem + 4096);
    if ((lane & 3) == 0) {
#pragma unroll
        for (int mf = 0; mf < 2; mf++)
#pragma unroll
            for (int h = 0; h < 2; h++) {
                int ri = mf * 2 + h;
                int rl = wm * 32 + mf * 16 + h * 8 + (lane >> 2);
                RM1[rl * 4 + wn] = m1[ri];
                RM2[rl * 4 + wn] = m2[ri];
                RK [rl * 4 + wn] = k1[ri];
            }
    }
    __syncthreads();
    if (tid < M_CTA) {
        float f1 = RM1[tid * 4], f2 = RM2[tid * 4]; int fk = RK[tid * 4];
#pragma unroll
        for (int w = 1; w < 4; w++) {
            float o1 = RM1[tid * 4 + w], o2 = RM2[tid * 4 + w]; int ok = RK[tid * 4 + w];
            if (o1 > f1) { f2 = fmaxf(f1, o2); f1 = o1; fk = ok; }
            else         { f2 = fmaxf(f2, o1); }
        }
        int grow = cta * M_CTA + tid;
        g_idx[grow] = fk;
        if (f1 - f2 < EPS_GAP) { int p = atomicAdd(&g_nflag, 1); g_flagrows[p] = grow; }
    }
}

// ---------------------------------------------------------------------------
// Kernel 3: parallel fallback — grid (64 tiles, 64 row-groups), bit-exact dist
// ---------------------------------------------------------------------------
__global__ __launch_bounds__(128)
void vq_fb_part(const float* __restrict__ z, const float* __restrict__ emb) {
    __shared__ float ec[128][68];
    __shared__ float zrow[64];
    __shared__ float b2c[128];
    __shared__ float wv[4];
    __shared__ int   wk[4];
    __shared__ float sa2;
    const int tid = threadIdx.x, t = blockIdx.x, grp = blockIdx.y;
    const int nf = g_nflag;
    if (grp >= nf) return;

    {
        const float4* g = (const float4*)(emb + (size_t)(t * 128 + tid) * D_DIM);
        float4* d = (float4*)&ec[tid][0];
#pragma unroll
        for (int i = 0; i < 16; i++) d[i] = g[i];
        b2c[tid] = g_b2[t * 128 + tid];
    }
    __syncthreads();

    for (int fi = grp; fi < nf; fi += FB_GRPS) {
        if (tid < 64) {
            int row = g_flagrows[fi];
            zrow[tid] = z[(size_t)(row >> 12) * (D_DIM * HW) + (size_t)tid * HW + (row & 4095)];
        }
        __syncthreads();
        if (tid < 32) {   // exact a2: XLA warp-tree order
            float tt = __fadd_rn(__fmul_rn(zrow[tid], zrow[tid]),
                                 __fmul_rn(zrow[tid + 32], zrow[tid + 32]));
#pragma unroll
            for (int off = 16; off >= 1; off >>= 1)
                tt = __fadd_rn(tt, __shfl_down_sync(0xFFFFFFFFu, tt, off));
            if (tid == 0) sa2 = tt;
        }
        __syncthreads();
        float acc = 0.0f;
        const float4* zb = (const float4*)&zrow[0];
        const float4* eb = (const float4*)&ec[tid][0];
#pragma unroll
        for (int i = 0; i < 16; i++) {
            float4 zv = zb[i], ev = eb[i];
            acc = fmaf(zv.x, ev.x, acc); acc = fmaf(zv.y, ev.y, acc);
            acc = fmaf(zv.z, ev.z, acc); acc = fmaf(zv.w, ev.w, acc);
        }
        float dist = __fadd_rn(__fsub_rn(sa2, __fmul_rn(2.0f, acc)), b2c[tid]);
        int   kidx = t * 128 + tid;
#pragma unroll
        for (int off = 16; off >= 1; off >>= 1) {
            float ov = __shfl_down_sync(0xFFFFFFFFu, dist, off);
            int   ok = __shfl_down_sync(0xFFFFFFFFu, kidx, off);
            if (ov < dist || (ov == dist && ok < kidx)) { dist = ov; kidx = ok; }
        }
        if ((tid & 31) == 0) { wv[tid >> 5] = dist; wk[tid >> 5] = kidx; }
        __syncthreads();
        if (tid == 0) {
            float bv = wv[0]; int bk = wk[0];
#pragma unroll
            for (int w = 1; w < 4; w++)
                if (wv[w] < bv || (wv[w] == bv && wk[w] < bk)) { bv = wv[w]; bk = wk[w]; }
            g_pval[(size_t)fi * 64 + t] = bv;
            g_pidx[(size_t)fi * 64 + t] = bk;
        }
        __syncthreads();
    }
}

// ---------------------------------------------------------------------------
// Kernel 4: fallback reduce — warp per flagged row over 64 tile results
// ---------------------------------------------------------------------------
__global__ void vq_fb_red() {
    int nf = g_nflag;
    int gw = (blockIdx.x * blockDim.x + threadIdx.x) >> 5;
    int lane = threadIdx.x & 31;
    int nwarps = (gridDim.x * blockDim.x) >> 5;
    for (int fi = gw; fi < nf; fi += nwarps) {
        float v1 = g_pval[(size_t)fi * 64 + lane];
        int   k1 = g_pidx[(size_t)fi * 64 + lane];
        float v2 = g_pval[(size_t)fi * 64 + lane + 32];
        int   k2 = g_pidx[(size_t)fi * 64 + lane + 32];
        if (v2 < v1 || (v2 == v1 && k2 < k1)) { v1 = v2; k1 = k2; }
#pragma unroll
        for (int off = 16; off >= 1; off >>= 1) {
            float ov = __shfl_down_sync(0xFFFFFFFFu, v1, off);
            int   ok = __shfl_down_sync(0xFFFFFFFFu, k1, off);
            if (ov < v1 || (ov == v1 && ok < k1)) { v1 = ov; k1 = ok; }
        }
        if (lane == 0) g_idx[g_flagrows[fi]] = k1;
    }
}

// ---------------------------------------------------------------------------
// Kernel 5: gather + STE z_q + indices + counts + loss
// ---------------------------------------------------------------------------
__global__ __launch_bounds__(256)
void vq_final(const float* __restrict__ z, const float* __restrict__ emb,
              float* __restrict__ out, int out_size) {
    const int row = blockIdx.x * 256 + threadIdx.x;
    const int b = row >> 12, hw = row & 4095;
    const int bidx = g_idx[row];
    const float* zp = z + (size_t)b * (D_DIM * HW) + hw;
    float* zq = out + (size_t)b * (D_DIM * HW) + hw;
    const bool wz = (out_size >= NZ);
    float ssq = 0.0f;
    const float4* eb4 = (const float4*)(emb + (size_t)bidx * D_DIM);
#pragma unroll
    for (int i = 0; i < 16; i++) {
        float4 ev = eb4[i];
#pragma unroll
        for (int j = 0; j < 4; j++) {
            int d = 4 * i + j;
            float e = (j == 0) ? ev.x : (j == 1) ? ev.y : (j == 2) ? ev.z : ev.w;
            float zv = zp[(size_t)d * HW];
            float df = __fsub_rn(zv, e);
            ssq = fmaf(df, df, ssq);
            if (wz) zq[(size_t)d * HW] = __fadd_rn(zv, __fsub_rn(e, zv));
        }
    }
    if (out_size >= NZ + NI) out[NZ + row] = (float)bidx;
    atomicAdd(&g_counts[bidx], 1);
#pragma unroll
    for (int o = 16; o > 0; o >>= 1) ssq += __shfl_down_sync(0xFFFFFFFFu, ssq, o);
    if ((threadIdx.x & 31) == 0) atomicAdd(&g_loss, ssq);
}

// ---------------------------------------------------------------------------
// Kernel 6: scalars
// ---------------------------------------------------------------------------
__global__ void vq_finalize(float* __restrict__ out, int out_size) {
    __shared__ float sH[256];
    __shared__ int   sU[256];
    const int tid = threadIdx.x;
    float H = 0.0f; int used = 0;
    for (int k = tid; k < K_CODES; k += 256) {
        float c = (float)g_counts[k];
        if (c > 0.0f) used++;
        float avg = c * (1.0f / (float)N_ROWS);
        H = fmaf(avg, logf(avg + 1e-10f), H);
    }
    sH[tid] = H; sU[tid] = used;
    __syncthreads();
    for (int s = 128; s > 0; s >>= 1) {
        if (tid < s) { sH[tid] += sH[tid + s]; sU[tid] += sU[tid + s]; }
        __syncthreads();
    }
    if (tid == 0 && out_size >= NZ + NI + 3) {
        out[NZ + NI + 0] = BETA * g_loss / (float)(N_ROWS * D_DIM);
        out[NZ + NI + 1] = expf(-sH[0]);
        out[NZ + NI + 2] = (float)sU[0] / (float)K_CODES;
    }
}

// ---------------------------------------------------------------------------
extern "C" void kernel_launch(void* const* d_in, const int* in_sizes, int n_in,
                              void* d_out, int out_size) {
    const float* z   = (const float*)d_in[0];
    const float* emb = (const float*)d_in[1];
    float* out = (float*)d_out;

    cudaFuncSetAttribute(vq_gemm, cudaFuncAttributeMaxDynamicSharedMemorySize, SM_TOT);

    vq_prep<<<(K_CODES * 32) / 256, 256>>>(emb);
    vq_gemm<<<CTAS, NTH, SM_TOT>>>(z);
    vq_fb_part<<<dim3(64, FB_GRPS), 128>>>(z, emb);
    vq_fb_red<<<64, 256>>>();
    vq_final<<<N_ROWS / 256, 256>>>(z, emb, out, out_size);
    vq_finalize<<<1, 256>>>(out, out_size);
}

// round 16
// speedup vs baseline: 1.3896x; 1.0499x over previous
#include <cuda_runtime.h>
#include <cuda_fp16.h>
#include <math.h>
#include <stdint.h>

// VanillaVQ: z_e (8,64,64,64) fp32, embedding (8192,64) fp32.
// Outputs (concat fp32): z_q | indices | commit_loss | perplexity | usage.

#define K_CODES 8192
#define D_DIM   64
#define N_ROWS  32768
#define HW      4096
#define BETA    0.25f
#define NZ (N_ROWS * D_DIM)
#define NI N_ROWS
#define EPS_GAP 3.5e-4f

// GEMM: S = fp16(z).fp16(e) - 0.5*b2 (bias as K-extension, KD=80)
// 2 CTAs/SM: 256 threads (8 warps: 4M x 2N), NT=128, single wave.
#define M_CTA  128
#define CTAS   256
#define NTH    256
#define NT     128          // codes per chunk
#define NCH    64
#define KROW   40           // u32 per B row in gmem (80 fp16 = 160B)
#define ARS    176          // smem row strides (odd*16 -> conflict-free ldmatrix)
#define BRS    176
#define SM_A   0                                     // 128*176 = 22528
#define SM_B(i) (22528u + (uint32_t)(i) * 22528u)    // 3 bufs of 128*176
#define SM_TOT 90112

#define FB_GRPS 64          // fallback row-groups (parallelism)

// ---------------- device scratch ----------------
__device__ float g_b2[K_CODES];
__device__ int   g_counts[K_CODES];
__device__ float g_loss;
__device__ int   g_nflag;
__device__ int   g_idx[N_ROWS];
__device__ int   g_flagrows[N_ROWS];
__device__ float g_pval[N_ROWS * 64];
__device__ int   g_pidx[N_ROWS * 64];
__device__ __align__(128) uint32_t g_E[K_CODES * KROW];   // 1.25MB fp16 image+bias

// ---------------- helpers ----------------
__device__ __forceinline__ uint32_t smem_u32(const void* p) {
    uint32_t a;
    asm("{ .reg .u64 t; cvta.to.shared.u64 t, %1; cvt.u32.u64 %0, t; }" : "=r"(a) : "l"(p));
    return a;
}
__device__ __forceinline__ uint32_t packh(float a, float b) {
    __half2 h = __floats2half2_rn(a, b);
    return *reinterpret_cast<uint32_t*>(&h);
}
__device__ __forceinline__ void ldm_x4(uint32_t* r, uint32_t addr) {
    asm volatile("ldmatrix.sync.aligned.m8n8.x4.shared.b16 {%0,%1,%2,%3}, [%4];"
                 : "=r"(r[0]), "=r"(r[1]), "=r"(r[2]), "=r"(r[3]) : "r"(addr));
}
__device__ __forceinline__ void ldm_x2(uint32_t* r, uint32_t addr) {
    asm volatile("ldmatrix.sync.aligned.m8n8.x2.shared.b16 {%0,%1}, [%2];"
                 : "=r"(r[0]), "=r"(r[1]) : "r"(addr));
}
__device__ __forceinline__ void mma16816(float* c, const uint32_t* a, const uint32_t* b) {
    asm volatile(
        "mma.sync.aligned.m16n8k16.row.col.f32.f16.f16.f32 "
        "{%0,%1,%2,%3}, {%4,%5,%6,%7}, {%8,%9}, {%0,%1,%2,%3};"
        : "+f"(c[0]), "+f"(c[1]), "+f"(c[2]), "+f"(c[3])
        : "r"(a[0]), "r"(a[1]), "r"(a[2]), "r"(a[3]), "r"(b[0]), "r"(b[1]));
}
__device__ __forceinline__ void cp16(uint32_t dst, const void* src) {
    uint64_t gs; asm("cvta.to.global.u64 %0, %1;" : "=l"(gs) : "l"(src));
    asm volatile("cp.async.cg.shared.global [%0], [%1], 16;" :: "r"(dst), "l"(gs));
}
// pack 10-bit id into low mantissa bits; quantum 2^10 ulp ~ 6e-5 << EPS.
// Within-quantum ambiguity => gap<EPS => flagged => exact fallback decides.
__device__ __forceinline__ float packid(float s, int idx) {
    return __int_as_float((__float_as_int(s) & ~0x3FF) | idx);
}
__device__ __forceinline__ void top2p(float p, float& m1, float& m2) {
    m2 = fmaxf(m2, fminf(p, m1));
    m1 = fmaxf(m1, p);
}

// ---------------------------------------------------------------------------
// Kernel 1 (merged prep): warp per code — b2 (XLA tree), image row
// [e | -0.5*b2 | zeros], zero counters.
// ---------------------------------------------------------------------------
__global__ void vq_prep(const float* __restrict__ emb) {
    int gtid = blockIdx.x * blockDim.x + threadIdx.x;
    int k = gtid >> 5, lane = gtid & 31;
    if (k < K_CODES) {
        const float* e = emb + (size_t)k * D_DIM;
        float t = __fadd_rn(__fmul_rn(e[lane], e[lane]),
                            __fmul_rn(e[lane + 32], e[lane + 32]));
#pragma unroll
        for (int off = 16; off >= 1; off >>= 1)
            t = __fadd_rn(t, __shfl_down_sync(0xFFFFFFFFu, t, off));
        uint32_t* row = g_E + (size_t)k * KROW;
        row[lane] = packh(e[2 * lane], e[2 * lane + 1]);   // dims 0..63
        if (lane < 8)
            row[32 + lane] = (lane == 0) ? packh(-0.5f * t, 0.0f) : 0u;
        if (lane == 0) { g_b2[k] = t; g_counts[k] = 0; }
    }
    if (gtid == 0) { g_loss = 0.0f; g_nflag = 0; }
}

// ---------------------------------------------------------------------------
// Kernel 2: fp16 HMMA GEMM (KD=80) + pipelined epilogue, 2 CTAs/SM
// ---------------------------------------------------------------------------
__device__ __forceinline__ void copy_chunk(int c, uint32_t dstbase, int tid) {
    const char* src = (const char*)g_E + (size_t)c * (NT * 160);
#pragma unroll
    for (int t = 0; t < 5; t++) {
        int idx = tid + t * NTH;                 // 0..1279
        int row = idx / 10, seg = idx % 10;
        cp16(dstbase + (uint32_t)row * BRS + (uint32_t)seg * 16,
             src + (size_t)row * 160 + (size_t)seg * 16);
    }
}

__global__ __launch_bounds__(NTH, 2)
void vq_gemm(const float* __restrict__ z) {
    extern __shared__ __align__(128) char smem[];
    const uint32_t sb = smem_u32(smem);
    const int tid = threadIdx.x, cta = blockIdx.x;
    const int lane = tid & 31, warp = tid >> 5;
    const int wm = warp >> 1, wn = warp & 1;      // 4(M) x 2(N)

    // ---- build A tile: row r (<128): [64 fp16 z | 1.0 | zeros] ----
    if (tid < M_CTA) {
        int grow = cta * M_CTA + tid;
        const float* zp = z + (size_t)(grow >> 12) * (D_DIM * HW) + (grow & 4095);
        char* ar = smem + SM_A + (size_t)tid * ARS;
#pragma unroll 8
        for (int d = 0; d < 64; d += 2)
            *(uint32_t*)(ar + 2 * d) = packh(zp[(size_t)d * HW], zp[(size_t)(d + 1) * HW]);
        *(uint32_t*)(ar + 128) = packh(1.0f, 0.0f);
#pragma unroll
        for (int j = 33; j < 44; j++)
            *(uint32_t*)(ar + 4 * j) = 0u;
    }
    __syncthreads();

    // ---- hoist A fragments (kernel-invariant): 40 regs ----
    const uint32_t Abase = sb + SM_A
        + (uint32_t)(wm * 32 + (lane & 7) + ((lane >> 3) & 1) * 8) * ARS
        + ((lane >> 4) & 1) * 16;
    uint32_t afr[5][2][4];
#pragma unroll
    for (int kk = 0; kk < 5; kk++)
#pragma unroll
        for (int mf = 0; mf < 2; mf++)
            ldm_x4(afr[kk][mf], Abase + (uint32_t)mf * (16 * ARS) + (uint32_t)kk * 32);

    copy_chunk(0, sb + SM_B(0), tid);
    asm volatile("cp.async.commit_group;");
    copy_chunk(1, sb + SM_B(1), tid);
    asm volatile("cp.async.commit_group;");

    // B lane addressing: x4 pairs two k-steps (lanes 16-31 at +32B)
    const uint32_t Brow0 = (uint32_t)(wn * 64 + (lane & 7)) * BRS
                         + ((lane >> 3) & 1) * 16 + ((lane >> 4) & 1) * 32;

    float m1[4], m2[4];
#pragma unroll
    for (int i = 0; i < 4; i++) { m1[i] = -3.4e38f; m2[i] = -3.4e38f; }

    float acc[2][2][4];    // ping-pong [parity][mf][v]

#define EPILOG(P, IDXBASE) do {                                           \
    const int _i0 = (IDXBASE), _i1 = (IDXBASE) | 1;                       \
    top2p(packid(acc[P][0][0], _i0), m1[0], m2[0]);                       \
    top2p(packid(acc[P][0][1], _i1), m1[0], m2[0]);                       \
    top2p(packid(acc[P][0][2], _i0), m1[1], m2[1]);                       \
    top2p(packid(acc[P][0][3], _i1), m1[1], m2[1]);                       \
    top2p(packid(acc[P][1][0], _i0), m1[2], m2[2]);                       \
    top2p(packid(acc[P][1][1], _i1), m1[2], m2[2]);                       \
    top2p(packid(acc[P][1][2], _i0), m1[3], m2[3]);                       \
    top2p(packid(acc[P][1][3], _i1), m1[3], m2[3]);                       \
} while (0)

    for (int c = 0; c < NCH; c++) {
        const uint32_t bbase = sb + SM_B(c % 3);
        if (c == NCH - 1) asm volatile("cp.async.wait_group 0;");
        else              asm volatile("cp.async.wait_group 1;");
        __syncthreads();     // chunk c visible; buf (c+2)%3 free
        if (c + 2 < NCH) {
            copy_chunk(c + 2, sb + SM_B((c + 2) % 3), tid);
            asm volatile("cp.async.commit_group;");
        }
        const int cbase = c << 4;    // chunk in bits [4..9]

#pragma unroll
        for (int nf = 0; nf < 8; nf++) {
            const int p = nf & 1;
            float* a0 = acc[p][0];
            float* a1 = acc[p][1];
#pragma unroll
            for (int v = 0; v < 4; v++) { a0[v] = 0.0f; a1[v] = 0.0f; }

            const uint32_t brow = bbase + Brow0 + (uint32_t)nf * (8 * BRS);
            uint32_t b4[4], b2f[2];
            ldm_x4(b4, brow);                       // ksteps 0,1
            mma16816(a0, afr[0][0], &b4[0]); mma16816(a1, afr[0][1], &b4[0]);
            mma16816(a0, afr[1][0], &b4[2]); mma16816(a1, afr[1][1], &b4[2]);
            ldm_x4(b4, brow + 64);                  // ksteps 2,3
            mma16816(a0, afr[2][0], &b4[0]); mma16816(a1, afr[2][1], &b4[0]);
            mma16816(a0, afr[3][0], &b4[2]); mma16816(a1, afr[3][1], &b4[2]);
            ldm_x2(b2f, brow + 128);                // kstep 4 (bias column)
            mma16816(a0, afr[4][0], b2f);  mma16816(a1, afr[4][1], b2f);

            if (nf > 0) EPILOG(1 - p, cbase | ((nf - 1) << 1));
        }
        EPILOG(1, cbase | (7 << 1));   // tail: nf=7 (parity 1)
    }
#undef EPILOG

    // decode per-lane indices (before quad merge: uses this lane's (lane&3))
    int k1[4];
#pragma unroll
    for (int i = 0; i < 4; i++) {
        int bits = __float_as_int(m1[i]) & 0x3FF;
        k1[i] = (bits >> 4) * NT + wn * 64 + (((bits >> 1) & 7) << 3)
              + (lane & 3) * 2 + (bits & 1);
    }

    // merge across the 4 quad lanes (same rows, different cols)
#pragma unroll
    for (int off = 1; off <= 2; off <<= 1) {
#pragma unroll
        for (int i = 0; i < 4; i++) {
            float om1 = __shfl_xor_sync(0xFFFFFFFFu, m1[i], off);
            float om2 = __shfl_xor_sync(0xFFFFFFFFu, m2[i], off);
            int   ok  = __shfl_xor_sync(0xFFFFFFFFu, k1[i], off);
            if (om1 > m1[i]) { m2[i] = fmaxf(m1[i], om2); m1[i] = om1; k1[i] = ok; }
            else             { m2[i] = fmaxf(m2[i], om1); }
        }
    }

    __syncthreads();   // smem reuse for cross-warp reduction
    float* RM1 = (float*)smem;                 // [128][2]
    float* RM2 = (float*)(smem + 1024);
    int*   RK  = (int*)(smem + 2048);
    if ((lane & 3) == 0) {
#pragma unroll
        for (int mf = 0; mf < 2; mf++)
#pragma unroll
            for (int h = 0; h < 2; h++) {
                int ri = mf * 2 + h;
                int rl = wm * 32 + mf * 16 + h * 8 + (lane >> 2);
                RM1[rl * 2 + wn] = m1[ri];
                RM2[rl * 2 + wn] = m2[ri];
                RK [rl * 2 + wn] = k1[ri];
            }
    }
    __syncthreads();
    if (tid < M_CTA) {
        float a1v = RM1[tid * 2],     a2v = RM2[tid * 2];     int ak = RK[tid * 2];
        float b1v = RM1[tid * 2 + 1], b2v = RM2[tid * 2 + 1]; int bk = RK[tid * 2 + 1];
        float f1, f2; int fk;
        if (b1v > a1v) { f1 = b1v; fk = bk; f2 = fmaxf(a1v, b2v); }
        else           { f1 = a1v; fk = ak; f2 = fmaxf(a2v, b1v); }
        int grow = cta * M_CTA + tid;
        g_idx[grow] = fk;
        if (f1 - f2 < EPS_GAP) { int p = atomicAdd(&g_nflag, 1); g_flagrows[p] = grow; }
    }
}

// ---------------------------------------------------------------------------
// Kernel 3: parallel fallback — grid (64 tiles, 64 row-groups), bit-exact dist
// ---------------------------------------------------------------------------
__global__ __launch_bounds__(128)
void vq_fb_part(const float* __restrict__ z, const float* __restrict__ emb) {
    __shared__ float ec[128][68];
    __shared__ float zrow[64];
    __shared__ float b2c[128];
    __shared__ float wv[4];
    __shared__ int   wk[4];
    __shared__ float sa2;
    const int tid = threadIdx.x, t = blockIdx.x, grp = blockIdx.y;
    const int nf = g_nflag;
    if (grp >= nf) return;

    {
        const float4* g = (const float4*)(emb + (size_t)(t * 128 + tid) * D_DIM);
        float4* d = (float4*)&ec[tid][0];
#pragma unroll
        for (int i = 0; i < 16; i++) d[i] = g[i];
        b2c[tid] = g_b2[t * 128 + tid];
    }
    __syncthreads();

    for (int fi = grp; fi < nf; fi += FB_GRPS) {
        if (tid < 64) {
            int row = g_flagrows[fi];
            zrow[tid] = z[(size_t)(row >> 12) * (D_DIM * HW) + (size_t)tid * HW + (row & 4095)];
        }
        __syncthreads();
        if (tid < 32) {   // exact a2: XLA warp-tree order
            float tt = __fadd_rn(__fmul_rn(zrow[tid], zrow[tid]),
                                 __fmul_rn(zrow[tid + 32], zrow[tid + 32]));
#pragma unroll
            for (int off = 16; off >= 1; off >>= 1)
                tt = __fadd_rn(tt, __shfl_down_sync(0xFFFFFFFFu, tt, off));
            if (tid == 0) sa2 = tt;
        }
        __syncthreads();
        float acc = 0.0f;
        const float4* zb = (const float4*)&zrow[0];
        const float4* eb = (const float4*)&ec[tid][0];
#pragma unroll
        for (int i = 0; i < 16; i++) {
            float4 zv = zb[i], ev = eb[i];
            acc = fmaf(zv.x, ev.x, acc); acc = fmaf(zv.y, ev.y, acc);
            acc = fmaf(zv.z, ev.z, acc); acc = fmaf(zv.w, ev.w, acc);
        }
        float dist = __fadd_rn(__fsub_rn(sa2, __fmul_rn(2.0f, acc)), b2c[tid]);
        int   kidx = t * 128 + tid;
#pragma unroll
        for (int off = 16; off >= 1; off >>= 1) {
            float ov = __shfl_down_sync(0xFFFFFFFFu, dist, off);
            int   ok = __shfl_down_sync(0xFFFFFFFFu, kidx, off);
            if (ov < dist || (ov == dist && ok < kidx)) { dist = ov; kidx = ok; }
        }
        if ((tid & 31) == 0) { wv[tid >> 5] = dist; wk[tid >> 5] = kidx; }
        __syncthreads();
        if (tid == 0) {
            float bv = wv[0]; int bk = wk[0];
#pragma unroll
            for (int w = 1; w < 4; w++)
                if (wv[w] < bv || (wv[w] == bv && wk[w] < bk)) { bv = wv[w]; bk = wk[w]; }
            g_pval[(size_t)fi * 64 + t] = bv;
            g_pidx[(size_t)fi * 64 + t] = bk;
        }
        __syncthreads();
    }
}

// ---------------------------------------------------------------------------
// Kernel 4: fallback reduce — warp per flagged row over 64 tile results
// ---------------------------------------------------------------------------
__global__ void vq_fb_red() {
    int nf = g_nflag;
    int gw = (blockIdx.x * blockDim.x + threadIdx.x) >> 5;
    int lane = threadIdx.x & 31;
    int nwarps = (gridDim.x * blockDim.x) >> 5;
    for (int fi = gw; fi < nf; fi += nwarps) {
        float v1 = g_pval[(size_t)fi * 64 + lane];
        int   k1 = g_pidx[(size_t)fi * 64 + lane];
        float v2 = g_pval[(size_t)fi * 64 + lane + 32];
        int   k2 = g_pidx[(size_t)fi * 64 + lane + 32];
        if (v2 < v1 || (v2 == v1 && k2 < k1)) { v1 = v2; k1 = k2; }
#pragma unroll
        for (int off = 16; off >= 1; off >>= 1) {
            float ov = __shfl_down_sync(0xFFFFFFFFu, v1, off);
            int   ok = __shfl_down_sync(0xFFFFFFFFu, k1, off);
            if (ov < v1 || (ov == v1 && ok < k1)) { v1 = ov; k1 = ok; }
        }
        if (lane == 0) g_idx[g_flagrows[fi]] = k1;
    }
}

// ---------------------------------------------------------------------------
// Kernel 5: gather + STE z_q + indices + counts + loss
// ---------------------------------------------------------------------------
__global__ __launch_bounds__(256)
void vq_final(const float* __restrict__ z, const float* __restrict__ emb,
              float* __restrict__ out, int out_size) {
    const int row = blockIdx.x * 256 + threadIdx.x;
    const int b = row >> 12, hw = row & 4095;
    const int bidx = g_idx[row];
    const float* zp = z + (size_t)b * (D_DIM * HW) + hw;
    float* zq = out + (size_t)b * (D_DIM * HW) + hw;
    const bool wz = (out_size >= NZ);
    float ssq = 0.0f;
    const float4* eb4 = (const float4*)(emb + (size_t)bidx * D_DIM);
#pragma unroll
    for (int i = 0; i < 16; i++) {
        float4 ev = eb4[i];
#pragma unroll
        for (int j = 0; j < 4; j++) {
            int d = 4 * i + j;
            float e = (j == 0) ? ev.x : (j == 1) ? ev.y : (j == 2) ? ev.z : ev.w;
            float zv = zp[(size_t)d * HW];
            float df = __fsub_rn(zv, e);
            ssq = fmaf(df, df, ssq);
            if (wz) zq[(size_t)d * HW] = __fadd_rn(zv, __fsub_rn(e, zv));
        }
    }
    if (out_size >= NZ + NI) out[NZ + row] = (float)bidx;
    atomicAdd(&g_counts[bidx], 1);
#pragma unroll
    for (int o = 16; o > 0; o >>= 1) ssq += __shfl_down_sync(0xFFFFFFFFu, ssq, o);
    if ((threadIdx.x & 31) == 0) atomicAdd(&g_loss, ssq);
}

// ---------------------------------------------------------------------------
// Kernel 6: scalars
// ---------------------------------------------------------------------------
__global__ void vq_finalize(float* __restrict__ out, int out_size) {
    __shared__ float sH[256];
    __shared__ int   sU[256];
    const int tid = threadIdx.x;
    float H = 0.0f; int used = 0;
    for (int k = tid; k < K_CODES; k += 256) {
        float c = (float)g_counts[k];
        if (c > 0.0f) used++;
        float avg = c * (1.0f / (float)N_ROWS);
        H = fmaf(avg, logf(avg + 1e-10f), H);
    }
    sH[tid] = H; sU[tid] = used;
    __syncthreads();
    for (int s = 128; s > 0; s >>= 1) {
        if (tid < s) { sH[tid] += sH[tid + s]; sU[tid] += sU[tid + s]; }
        __syncthreads();
    }
    if (tid == 0 && out_size >= NZ + NI + 3) {
        out[NZ + NI + 0] = BETA * g_loss / (float)(N_ROWS * D_DIM);
        out[NZ + NI + 1] = expf(-sH[0]);
        out[NZ + NI + 2] = (float)sU[0] / (float)K_CODES;
    }
}

// ---------------------------------------------------------------------------
extern "C" void kernel_launch(void* const* d_in, const int* in_sizes, int n_in,
                              void* d_out, int out_size) {
    const float* z   = (const float*)d_in[0];
    const float* emb = (const float*)d_in[1];
    float* out = (float*)d_out;

    cudaFuncSetAttribute(vq_gemm, cudaFuncAttributeMaxDynamicSharedMemorySize, SM_TOT);

    vq_prep<<<(K_CODES * 32) / 256, 256>>>(emb);
    vq_gemm<<<CTAS, NTH, SM_TOT>>>(z);
    vq_fb_part<<<dim3(64, FB_GRPS), 128>>>(z, emb);
    vq_fb_red<<<64, 256>>>();
    vq_final<<<N_ROWS / 256, 256>>>(z, emb, out, out_size);
    vq_finalize<<<1, 256>>>(out, out_size);
}

// round 17
// speedup vs baseline: 1.4635x; 1.0532x over previous
#include <cuda_runtime.h>
#include <cuda_fp16.h>
#include <math.h>
#include <stdint.h>

// VanillaVQ: z_e (8,64,64,64) fp32, embedding (8192,64) fp32.
// Outputs (concat fp32): z_q | indices | commit_loss | perplexity | usage.

#define K_CODES 8192
#define D_DIM   64
#define N_ROWS  32768
#define HW      4096
#define BETA    0.25f
#define NZ (N_ROWS * D_DIM)
#define NI N_ROWS
#define EPS_GAP 3.5e-4f

// GEMM: S = fp16(z).fp16(e) - 0.5*b2 (bias in epilogue on fma pipe, KD=64)
// 2 CTAs/SM: 256 threads (8 warps: 4M x 2N), NT=128, single wave.
#define M_CTA  128
#define CTAS   256
#define NTH    256
#define NT     128          // codes per chunk
#define NCH    64
#define ARS    144          // smem row strides (odd*16 -> conflict-free ldmatrix)
#define BRS    144
#define SM_A   0                                     // 128*144 = 18432
#define SM_B(i) (18432u + (uint32_t)(i) * 18432u)    // 3 bufs of 128*144
#define SM_B2  73728u                                // 32KB b2 copy
#define SM_TOT 106496

#define FB_GRPS 64          // fallback row-groups (parallelism)

// ---------------- device scratch ----------------
__device__ float g_b2[K_CODES];
__device__ int   g_counts[K_CODES];
__device__ float g_loss;
__device__ int   g_nflag;
__device__ int   g_flagrows[N_ROWS];
__device__ unsigned long long g_fbkey[N_ROWS];   // (orderable dist)<<32 | idx
__device__ __align__(128) uint32_t g_E[K_CODES * 32];   // 1MB fp16 image of emb

// ---------------- helpers ----------------
__device__ __forceinline__ uint32_t smem_u32(const void* p) {
    uint32_t a;
    asm("{ .reg .u64 t; cvta.to.shared.u64 t, %1; cvt.u32.u64 %0, t; }" : "=r"(a) : "l"(p));
    return a;
}
__device__ __forceinline__ uint32_t packh(float a, float b) {
    __half2 h = __floats2half2_rn(a, b);
    return *reinterpret_cast<uint32_t*>(&h);
}
__device__ __forceinline__ void ldm_x4(uint32_t* r, uint32_t addr) {
    asm volatile("ldmatrix.sync.aligned.m8n8.x4.shared.b16 {%0,%1,%2,%3}, [%4];"
                 : "=r"(r[0]), "=r"(r[1]), "=r"(r[2]), "=r"(r[3]) : "r"(addr));
}
__device__ __forceinline__ void mma16816(float* c, const uint32_t* a, const uint32_t* b) {
    asm volatile(
        "mma.sync.aligned.m16n8k16.row.col.f32.f16.f16.f32 "
        "{%0,%1,%2,%3}, {%4,%5,%6,%7}, {%8,%9}, {%0,%1,%2,%3};"
        : "+f"(c[0]), "+f"(c[1]), "+f"(c[2]), "+f"(c[3])
        : "r"(a[0]), "r"(a[1]), "r"(a[2]), "r"(a[3]), "r"(b[0]), "r"(b[1]));
}
__device__ __forceinline__ void cp16(uint32_t dst, const void* src) {
    uint64_t gs; asm("cvta.to.global.u64 %0, %1;" : "=l"(gs) : "l"(src));
    asm volatile("cp.async.cg.shared.global [%0], [%1], 16;" :: "r"(dst), "l"(gs));
}
// pack 10-bit id into low mantissa bits; quantum 2^10 ulp ~ 6e-5 << EPS.
__device__ __forceinline__ float packid(float s, int idx) {
    return __int_as_float((__float_as_int(s) & ~0x3FF) | idx);
}
__device__ __forceinline__ void top2p(float p, float& m1, float& m2) {
    m2 = fmaxf(m2, fminf(p, m1));
    m1 = fmaxf(m1, p);
}
// order-preserving uint transform for fp32 (handles negatives)
__device__ __forceinline__ uint32_t ford(float f) {
    uint32_t b = __float_as_uint(f);
    return b ^ ((b >> 31) ? 0xFFFFFFFFu : 0x80000000u);
}

// ---------------------------------------------------------------------------
// Kernel 1 (merged prep): warp per code — b2 (XLA tree), fp16 image, zeroing
// ---------------------------------------------------------------------------
__global__ void vq_prep(const float* __restrict__ emb) {
    int gtid = blockIdx.x * blockDim.x + threadIdx.x;
    int k = gtid >> 5, lane = gtid & 31;
    if (k < K_CODES) {
        const float* e = emb + (size_t)k * D_DIM;
        float t = __fadd_rn(__fmul_rn(e[lane], e[lane]),
                            __fmul_rn(e[lane + 32], e[lane + 32]));
#pragma unroll
        for (int off = 16; off >= 1; off >>= 1)
            t = __fadd_rn(t, __shfl_down_sync(0xFFFFFFFFu, t, off));
        g_E[(size_t)k * 32 + lane] = packh(e[2 * lane], e[2 * lane + 1]);
        if (lane == 0) { g_b2[k] = t; g_counts[k] = 0; }
    }
    if (gtid == 0) { g_loss = 0.0f; g_nflag = 0; }
}

// ---------------------------------------------------------------------------
// Kernel 2: fp16 HMMA GEMM (KD=64) + epilogue bias on fma pipe, 2 CTAs/SM
// ---------------------------------------------------------------------------
__device__ __forceinline__ void copy_chunk(int c, uint32_t dstbase, int tid) {
    const char* src = (const char*)g_E + (size_t)c * (NT * 128);
#pragma unroll
    for (int t = 0; t < 4; t++) {
        int idx = tid + t * NTH;                 // 0..1023
        int row = idx >> 3, seg = idx & 7;
        cp16(dstbase + (uint32_t)row * BRS + (uint32_t)seg * 16,
             src + (size_t)row * 128 + (size_t)seg * 16);
    }
}

__global__ __launch_bounds__(NTH, 2)
void vq_gemm(const float* __restrict__ z) {
    extern __shared__ __align__(128) char smem[];
    const uint32_t sb = smem_u32(smem);
    const int tid = threadIdx.x, cta = blockIdx.x;
    const int lane = tid & 31, warp = tid >> 5;
    const int wm = warp >> 1, wn = warp & 1;      // 4(M) x 2(N)

    // ---- build A tile: row r (<128): 64 fp16 of z (+ pad) ----
    if (tid < M_CTA) {
        int grow = cta * M_CTA + tid;
        const float* zp = z + (size_t)(grow >> 12) * (D_DIM * HW) + (grow & 4095);
        char* ar = smem + SM_A + (size_t)tid * ARS;
#pragma unroll 8
        for (int d = 0; d < 64; d += 2)
            *(uint32_t*)(ar + 2 * d) = packh(zp[(size_t)d * HW], zp[(size_t)(d + 1) * HW]);
#pragma unroll
        for (int j = 32; j < 36; j++)
            *(uint32_t*)(ar + 4 * j) = 0u;
    }
    __syncthreads();

    // ---- hoist A fragments (kernel-invariant): 32 regs ----
    const uint32_t Abase = sb + SM_A
        + (uint32_t)(wm * 32 + (lane & 7) + ((lane >> 3) & 1) * 8) * ARS
        + ((lane >> 4) & 1) * 16;
    uint32_t afr[4][2][4];
#pragma unroll
    for (int kk = 0; kk < 4; kk++)
#pragma unroll
        for (int mf = 0; mf < 2; mf++)
            ldm_x4(afr[kk][mf], Abase + (uint32_t)mf * (16 * ARS) + (uint32_t)kk * 32);

    // b2 -> smem (32KB) grouped with chunk 0
    {
        const char* bsrc = (const char*)g_b2;
#pragma unroll
        for (int t = 0; t < 8; t++) {
            int idx = tid + t * NTH;
            cp16(sb + SM_B2 + (uint32_t)idx * 16, bsrc + (size_t)idx * 16);
        }
    }
    copy_chunk(0, sb + SM_B(0), tid);
    asm volatile("cp.async.commit_group;");
    copy_chunk(1, sb + SM_B(1), tid);
    asm volatile("cp.async.commit_group;");

    // B lane addressing: x4 pairs two k-steps (lanes 16-31 at +32B)
    const uint32_t Brow0 = (uint32_t)(wn * 64 + (lane & 7)) * BRS
                         + ((lane >> 3) & 1) * 16 + ((lane >> 4) & 1) * 32;
    const uint32_t b2thr = SM_B2 + (uint32_t)(wn * 64 + (lane & 3) * 2) * 4;

    float m1[4], m2[4];
#pragma unroll
    for (int i = 0; i < 4; i++) { m1[i] = -3.4e38f; m2[i] = -3.4e38f; }

    float acc[2][2][4];    // ping-pong [parity][mf][v]

#define EPILOG(P, NF, IDXBASE) do {                                       \
    float2 _bv = *(const float2*)(b2p + (NF) * 32);                       \
    const int _i0 = (IDXBASE), _i1 = (IDXBASE) | 1;                       \
    top2p(packid(fmaf(-0.5f, _bv.x, acc[P][0][0]), _i0), m1[0], m2[0]);   \
    top2p(packid(fmaf(-0.5f, _bv.y, acc[P][0][1]), _i1), m1[0], m2[0]);   \
    top2p(packid(fmaf(-0.5f, _bv.x, acc[P][0][2]), _i0), m1[1], m2[1]);   \
    top2p(packid(fmaf(-0.5f, _bv.y, acc[P][0][3]), _i1), m1[1], m2[1]);   \
    top2p(packid(fmaf(-0.5f, _bv.x, acc[P][1][0]), _i0), m1[2], m2[2]);   \
    top2p(packid(fmaf(-0.5f, _bv.y, acc[P][1][1]), _i1), m1[2], m2[2]);   \
    top2p(packid(fmaf(-0.5f, _bv.x, acc[P][1][2]), _i0), m1[3], m2[3]);   \
    top2p(packid(fmaf(-0.5f, _bv.y, acc[P][1][3]), _i1), m1[3], m2[3]);   \
} while (0)

    for (int c = 0; c < NCH; c++) {
        const uint32_t bbase = sb + SM_B(c % 3);
        if (c == NCH - 1) asm volatile("cp.async.wait_group 0;");
        else              asm volatile("cp.async.wait_group 1;");
        __syncthreads();     // chunk c visible; buf (c+2)%3 free
        if (c + 2 < NCH) {
            copy_chunk(c + 2, sb + SM_B((c + 2) % 3), tid);
            asm volatile("cp.async.commit_group;");
        }
        const int cbase = c << 4;
        const char* b2p = smem + b2thr + (uint32_t)c * (NT * 4);

#pragma unroll
        for (int nf = 0; nf < 8; nf++) {
            const int p = nf & 1;
            float* a0 = acc[p][0];
            float* a1 = acc[p][1];
#pragma unroll
            for (int v = 0; v < 4; v++) { a0[v] = 0.0f; a1[v] = 0.0f; }

            const uint32_t brow = bbase + Brow0 + (uint32_t)nf * (8 * BRS);
            uint32_t b4[4];
            ldm_x4(b4, brow);                       // ksteps 0,1
            mma16816(a0, afr[0][0], &b4[0]); mma16816(a1, afr[0][1], &b4[0]);
            mma16816(a0, afr[1][0], &b4[2]); mma16816(a1, afr[1][1], &b4[2]);
            ldm_x4(b4, brow + 64);                  // ksteps 2,3
            mma16816(a0, afr[2][0], &b4[0]); mma16816(a1, afr[2][1], &b4[0]);
            mma16816(a0, afr[3][0], &b4[2]); mma16816(a1, afr[3][1], &b4[2]);

            if (nf > 0) EPILOG(1 - p, nf - 1, cbase | ((nf - 1) << 1));
        }
        EPILOG(1, 7, cbase | (7 << 1));   // tail: nf=7 (parity 1)
    }
#undef EPILOG

    // decode per-lane indices (before quad merge: uses this lane's (lane&3))
    int k1[4];
#pragma unroll
    for (int i = 0; i < 4; i++) {
        int bits = __float_as_int(m1[i]) & 0x3FF;
        k1[i] = (bits >> 4) * NT + wn * 64 + (((bits >> 1) & 7) << 3)
              + (lane & 3) * 2 + (bits & 1);
    }

    // merge across the 4 quad lanes (same rows, different cols)
#pragma unroll
    for (int off = 1; off <= 2; off <<= 1) {
#pragma unroll
        for (int i = 0; i < 4; i++) {
            float om1 = __shfl_xor_sync(0xFFFFFFFFu, m1[i], off);
            float om2 = __shfl_xor_sync(0xFFFFFFFFu, m2[i], off);
            int   ok  = __shfl_xor_sync(0xFFFFFFFFu, k1[i], off);
            if (om1 > m1[i]) { m2[i] = fmaxf(m1[i], om2); m1[i] = om1; k1[i] = ok; }
            else             { m2[i] = fmaxf(m2[i], om1); }
        }
    }

    __syncthreads();   // smem reuse for cross-warp reduction
    float* RM1 = (float*)smem;                 // [128][2]
    float* RM2 = (float*)(smem + 1024);
    int*   RK  = (int*)(smem + 2048);
    if ((lane & 3) == 0) {
#pragma unroll
        for (int mf = 0; mf < 2; mf++)
#pragma unroll
            for (int h = 0; h < 2; h++) {
                int ri = mf * 2 + h;
                int rl = wm * 32 + mf * 16 + h * 8 + (lane >> 2);
                RM1[rl * 2 + wn] = m1[ri];
                RM2[rl * 2 + wn] = m2[ri];
                RK [rl * 2 + wn] = k1[ri];
            }
    }
    __syncthreads();
    if (tid < M_CTA) {
        float a1v = RM1[tid * 2],     a2v = RM2[tid * 2];     int ak = RK[tid * 2];
        float b1v = RM1[tid * 2 + 1], b2v = RM2[tid * 2 + 1]; int bk = RK[tid * 2 + 1];
        float f1, f2; int fk;
        if (b1v > a1v) { f1 = b1v; fk = bk; f2 = fmaxf(a1v, b2v); }
        else           { f1 = a1v; fk = ak; f2 = fmaxf(a2v, b1v); }
        int grow = cta * M_CTA + tid;
        bool flag = (f1 - f2 < EPS_GAP);
        g_fbkey[grow] = flag ? ~0ull : (unsigned long long)(uint32_t)fk;
        if (flag) { int p = atomicAdd(&g_nflag, 1); g_flagrows[p] = grow; }
    }
}

// ---------------------------------------------------------------------------
// Kernel 3: parallel fallback — grid (64 tiles, 64 row-groups); bit-exact
// dist; per-tile winner merged globally via atomicMin on packed key.
// ---------------------------------------------------------------------------
__global__ __launch_bounds__(128)
void vq_fb_part(const float* __restrict__ z, const float* __restrict__ emb) {
    __shared__ float ec[128][68];
    __shared__ float zrow[64];
    __shared__ float b2c[128];
    __shared__ float wv[4];
    __shared__ int   wk[4];
    __shared__ float sa2;
    const int tid = threadIdx.x, t = blockIdx.x, grp = blockIdx.y;
    const int nf = g_nflag;
    if (grp >= nf) return;

    {
        const float4* g = (const float4*)(emb + (size_t)(t * 128 + tid) * D_DIM);
        float4* d = (float4*)&ec[tid][0];
#pragma unroll
        for (int i = 0; i < 16; i++) d[i] = g[i];
        b2c[tid] = g_b2[t * 128 + tid];
    }
    __syncthreads();

    for (int fi = grp; fi < nf; fi += FB_GRPS) {
        const int row = g_flagrows[fi];
        if (tid < 64)
            zrow[tid] = z[(size_t)(row >> 12) * (D_DIM * HW) + (size_t)tid * HW + (row & 4095)];
        __syncthreads();
        if (tid < 32) {   // exact a2: XLA warp-tree order
            float tt = __fadd_rn(__fmul_rn(zrow[tid], zrow[tid]),
                                 __fmul_rn(zrow[tid + 32], zrow[tid + 32]));
#pragma unroll
            for (int off = 16; off >= 1; off >>= 1)
                tt = __fadd_rn(tt, __shfl_down_sync(0xFFFFFFFFu, tt, off));
            if (tid == 0) sa2 = tt;
        }
        __syncthreads();
        float acc = 0.0f;
        const float4* zb = (const float4*)&zrow[0];
        const float4* eb = (const float4*)&ec[tid][0];
#pragma unroll
        for (int i = 0; i < 16; i++) {
            float4 zv = zb[i], ev = eb[i];
            acc = fmaf(zv.x, ev.x, acc); acc = fmaf(zv.y, ev.y, acc);
            acc = fmaf(zv.z, ev.z, acc); acc = fmaf(zv.w, ev.w, acc);
        }
        float dist = __fadd_rn(__fsub_rn(sa2, __fmul_rn(2.0f, acc)), b2c[tid]);
        int   kidx = t * 128 + tid;
#pragma unroll
        for (int off = 16; off >= 1; off >>= 1) {
            float ov = __shfl_down_sync(0xFFFFFFFFu, dist, off);
            int   ok = __shfl_down_sync(0xFFFFFFFFu, kidx, off);
            if (ov < dist || (ov == dist && ok < kidx)) { dist = ov; kidx = ok; }
        }
        if ((tid & 31) == 0) { wv[tid >> 5] = dist; wk[tid >> 5] = kidx; }
        __syncthreads();
        if (tid == 0) {
            float bv = wv[0]; int bk = wk[0];
#pragma unroll
            for (int w = 1; w < 4; w++)
                if (wv[w] < bv || (wv[w] == bv && wk[w] < bk)) { bv = wv[w]; bk = wk[w]; }
            unsigned long long key = ((unsigned long long)ford(bv) << 32)
                                   | (unsigned long long)(uint32_t)bk;
            atomicMin(&g_fbkey[row], key);
        }
        __syncthreads();
    }
}

// ---------------------------------------------------------------------------
// Kernel 4: gather + STE z_q + indices + counts + loss
// ---------------------------------------------------------------------------
__global__ __launch_bounds__(256)
void vq_final(const float* __restrict__ z, const float* __restrict__ emb,
              float* __restrict__ out, int out_size) {
    const int row = blockIdx.x * 256 + threadIdx.x;
    const int b = row >> 12, hw = row & 4095;
    const int bidx = (int)(uint32_t)(g_fbkey[row] & 0xFFFFFFFFull);
    const float* zp = z + (size_t)b * (D_DIM * HW) + hw;
    float* zq = out + (size_t)b * (D_DIM * HW) + hw;
    const bool wz = (out_size >= NZ);
    float ssq = 0.0f;
    const float4* eb4 = (const float4*)(emb + (size_t)bidx * D_DIM);
#pragma unroll
    for (int i = 0; i < 16; i++) {
        float4 ev = eb4[i];
#pragma unroll
        for (int j = 0; j < 4; j++) {
            int d = 4 * i + j;
            float e = (j == 0) ? ev.x : (j == 1) ? ev.y : (j == 2) ? ev.z : ev.w;
            float zv = zp[(size_t)d * HW];
            float df = __fsub_rn(zv, e);
            ssq = fmaf(df, df, ssq);
            if (wz) zq[(size_t)d * HW] = __fadd_rn(zv, __fsub_rn(e, zv));
        }
    }
    if (out_size >= NZ + NI) out[NZ + row] = (float)bidx;
    atomicAdd(&g_counts[bidx], 1);
#pragma unroll
    for (int o = 16; o > 0; o >>= 1) ssq += __shfl_down_sync(0xFFFFFFFFu, ssq, o);
    if ((threadIdx.x & 31) == 0) atomicAdd(&g_loss, ssq);
}

// ---------------------------------------------------------------------------
// Kernel 5: scalars
// ---------------------------------------------------------------------------
__global__ void vq_finalize(float* __restrict__ out, int out_size) {
    __shared__ float sH[256];
    __shared__ int   sU[256];
    const int tid = threadIdx.x;
    float H = 0.0f; int used = 0;
    for (int k = tid; k < K_CODES; k += 256) {
        float c = (float)g_counts[k];
        if (c > 0.0f) used++;
        float avg = c * (1.0f / (float)N_ROWS);
        H = fmaf(avg, logf(avg + 1e-10f), H);
    }
    sH[tid] = H; sU[tid] = used;
    __syncthreads();
    for (int s = 128; s > 0; s >>= 1) {
        if (tid < s) { sH[tid] += sH[tid + s]; sU[tid] += sU[tid + s]; }
        __syncthreads();
    }
    if (tid == 0 && out_size >= NZ + NI + 3) {
        out[NZ + NI + 0] = BETA * g_loss / (float)(N_ROWS * D_DIM);
        out[NZ + NI + 1] = expf(-sH[0]);
        out[NZ + NI + 2] = (float)sU[0] / (float)K_CODES;
    }
}

// ---------------------------------------------------------------------------
extern "C" void kernel_launch(void* const* d_in, const int* in_sizes, int n_in,
                              void* d_out, int out_size) {
    const float* z   = (const float*)d_in[0];
    const float* emb = (const float*)d_in[1];
    float* out = (float*)d_out;

    cudaFuncSetAttribute(vq_gemm, cudaFuncAttributeMaxDynamicSharedMemorySize, SM_TOT);

    vq_prep<<<(K_CODES * 32) / 256, 256>>>(emb);
    vq_gemm<<<CTAS, NTH, SM_TOT>>>(z);
    vq_fb_part<<<dim3(64, FB_GRPS), 128>>>(z, emb);
    vq_final<<<N_ROWS / 256, 256>>>(z, emb, out, out_size);
    vq_finalize<<<1, 256>>>(out, out_size);
}